// round 5
// baseline (speedup 1.0000x reference)
#include <cuda_runtime.h>
#include <cuda_fp16.h>

#define Bz 2
#define Vn 4
#define Cn 32
#define Hf 64
#define Wf 64
#define Dv 64
#define Pn (Dv*Dv*Dv)
#define HWC (Hf*Wf*Cn)

// Tile: 32 (x) x 4 (y) x 1 (z) = 128 points per block, 512 threads.
__device__ float  g_featT[Bz*Vn*HWC];                    // [bv][pix][c] fp32
__device__ __half g_Q[(size_t)Bz*Vn*4096*128];           // [bv][tex][tap4][c32] fp16
__device__ float  g_cam[Bz*Vn][16];

struct Rec { float w; int off; };                        // 8B: tap weight + quad offset (halves)

// ---------------------------------------------------------------------------
// k1: transpose [BV,C,H,W] -> [BV,H,W,C]; block 0 folds camera constants.
// ---------------------------------------------------------------------------
__global__ void prep_kernel(const float* __restrict__ f,
                            const float* __restrict__ R, const float* __restrict__ T,
                            const float* __restrict__ K, const float* __restrict__ root) {
    int idx = blockIdx.x * blockDim.x + threadIdx.x;
    int c   = idx & 31;
    int pix = (idx >> 5) & (Hf*Wf - 1);
    int bv  = idx >> 17;
    g_featT[idx] = f[(bv*Cn + c)*(Hf*Wf) + pix];

    if (blockIdx.x == 0 && threadIdx.x < Bz*Vn) {
        int i = threadIdx.x, b = i / Vn;
        const float* Ri = R + i*9; const float* Ti = T + i*3;
        const float* Ki = K + i*9; const float* rb = root + b*3;
        float* o = g_cam[i];
        #pragma unroll
        for (int r = 0; r < 9; r++) o[r] = Ri[r];
        #pragma unroll
        for (int r = 0; r < 3; r++)
            o[9+r] = Ri[r*3+0]*rb[0] + Ri[r*3+1]*rb[1] + Ri[r*3+2]*rb[2] + Ti[r];
        o[12] = Ki[0]; o[13] = Ki[4]; o[14] = Ki[2]; o[15] = Ki[5];
    }
}

// ---------------------------------------------------------------------------
// k2: quad-pack to fp16: Q[bv][tex][t][c] = featT[bv][clamped neighbor][c].
// Thread = (bv, tex, tap, channel-octet): 2x float4 read, 1x uint4 write.
// ---------------------------------------------------------------------------
__global__ void qpack_kernel() {
    int idx = blockIdx.x * blockDim.x + threadIdx.x;     // 524288
    int cq  = idx & 3;
    int t   = (idx >> 2) & 3;
    int tex = (idx >> 4) & 4095;
    int bv  = idx >> 16;
    int y = tex >> 6, x = tex & 63;
    int ny = min(y + (t >> 1), 63);
    int nx = min(x + (t & 1), 63);
    const float* src = g_featT + ((size_t)bv*4096 + ny*64 + nx)*Cn + cq*8;
    float4 a = *reinterpret_cast<const float4*>(src);
    float4 b = *reinterpret_cast<const float4*>(src + 4);
    __half2 h0 = __floats2half2_rn(a.x, a.y);
    __half2 h1 = __floats2half2_rn(a.z, a.w);
    __half2 h2 = __floats2half2_rn(b.x, b.y);
    __half2 h3 = __floats2half2_rn(b.z, b.w);
    uint4 u;
    u.x = *reinterpret_cast<unsigned*>(&h0);
    u.y = *reinterpret_cast<unsigned*>(&h1);
    u.z = *reinterpret_cast<unsigned*>(&h2);
    u.w = *reinterpret_cast<unsigned*>(&h3);
    *reinterpret_cast<uint4*>(g_Q + ((size_t)(bv*4096 + tex)*128 + t*32 + cq*8)) = u;
}

// ---------------------------------------------------------------------------
// Main kernel.
// Phase 1: project 128 pts x 4 views; remap bilinear weights onto a clamped
//          quad base; write {w, off} records (4 taps) to SMEM.
// Phase 2: one LDG.64/warp per point-view (256B contiguous = 2 lines);
//          lane = (tap, channel-quad); shuffle-reduce taps.
// Phase 3: conflict-free scalar LDS + fully coalesced STG.32.
// ---------------------------------------------------------------------------
__global__ __launch_bounds__(512, 2) void sample_kernel(float* __restrict__ out) {
    __shared__ float s_cam[128];                 // 4 views x 16
    __shared__ Rec   s_rec[128][Vn][4];          // [pl][v][tap]
    __shared__ float s_acc[128][Cn + 1];         // stride 33 -> conflict-free

    const int tid = threadIdx.x;
    const int bid = blockIdx.x;
    const int b   = bid >> 11;
    const int t   = bid & 2047;
    const int x0t = (t & 1) * 32;
    const int y0t = ((t >> 1) & 15) * 4;
    const int z0t = t >> 5;

    if (tid < 128) s_cam[tid] = reinterpret_cast<const float*>(g_cam)[b*64 + tid];
    __syncthreads();

    // -------- Phase 1 --------
    {
        const int pl = tid >> 2;
        const int v  = tid & 3;
        const int xi = x0t + (pl & 31);
        const int yi = y0t + (pl >> 5);
        const int zi = z0t;

        const float wx = (xi * (1.0f/63.0f) - 0.5f) * 0.2f;
        const float wy = (yi * (1.0f/63.0f) - 0.5f) * 0.2f;
        const float wz = (zi * (1.0f/63.0f) - 0.5f) * 0.2f;

        const float* cam = &s_cam[v*16];
        const float Xc = cam[0]*wx + cam[1]*wy + cam[2]*wz + cam[9];
        const float Yc = cam[3]*wx + cam[4]*wy + cam[5]*wz + cam[10];
        const float Zc = cam[6]*wx + cam[7]*wy + cam[8]*wz + cam[11];
        const float zc = fmaxf(Zc, 1e-5f);

        const float u  = (Xc * cam[12]) / zc + cam[14];
        const float vv = (Yc * cam[13]) / zc + cam[15];
        const float px = u  * (64.0f/255.0f) - 0.5f;
        const float py = vv * (64.0f/255.0f) - 0.5f;

        const float x0f = floorf(px), y0f = floorf(py);
        const float fx1 = px - x0f,   fy1 = py - y0f;
        const float fx0 = 1.0f - fx1, fy0 = 1.0f - fy1;
        const int ix0 = (int)x0f, iy0 = (int)y0f;
        const int ix1 = ix0 + 1,  iy1 = iy0 + 1;

        const float mx0 = (ix0 >= 0 && ix0 < Wf) ? fx0 : 0.0f;
        const float mx1 = (ix1 >= 0 && ix1 < Wf) ? fx1 : 0.0f;
        const float my0 = (iy0 >= 0 && iy0 < Hf) ? fy0 * 0.25f : 0.0f;
        const float my1 = (iy1 >= 0 && iy1 < Hf) ? fy1 * 0.25f : 0.0f;

        // clamped quad base + weight remap (matches independent-clamp semantics)
        const int bx = min(max(ix0, 0), Wf-2);
        const int by = min(max(iy0, 0), Hf-2);
        const float wqx0 = (ix0 == bx)   ? mx0 : ((ix1 == bx)   ? mx1 : 0.0f);
        const float wqx1 = (ix1 == bx+1) ? mx1 : ((ix0 == bx+1) ? mx0 : 0.0f);
        const float wqy0 = (iy0 == by)   ? my0 : ((iy1 == by)   ? my1 : 0.0f);
        const float wqy1 = (iy1 == by+1) ? my1 : ((iy0 == by+1) ? my0 : 0.0f);

        const int off = (by*Wf + bx) * 128;      // halves
        s_rec[pl][v][0] = Rec{wqy0*wqx0, off};
        s_rec[pl][v][1] = Rec{wqy0*wqx1, off};
        s_rec[pl][v][2] = Rec{wqy1*wqx0, off};
        s_rec[pl][v][3] = Rec{wqy1*wqx1, off};
    }
    __syncthreads();

    // -------- Phase 2 --------
    {
        const int w    = tid >> 5;
        const int lane = tid & 31;
        const int tap  = lane >> 3;
        float4 acc[8];
        #pragma unroll
        for (int i = 0; i < 8; i++) acc[i] = make_float4(0.f,0.f,0.f,0.f);

        const __half* qb = g_Q + (size_t)b*Vn*4096*128 + (size_t)(lane*4);
        #pragma unroll
        for (int v = 0; v < Vn; v++) {
            const __half* qv = qb + (size_t)v*4096*128;
            #pragma unroll
            for (int i = 0; i < 8; i++) {
                const int pl = w*8 + i;
                const Rec r = s_rec[pl][v][tap];
                const uint2 d = *reinterpret_cast<const uint2*>(qv + r.off);
                const float2 f0 = __half22float2(*reinterpret_cast<const __half2*>(&d.x));
                const float2 f1 = __half22float2(*reinterpret_cast<const __half2*>(&d.y));
                acc[i].x = fmaf(r.w, f0.x, acc[i].x);
                acc[i].y = fmaf(r.w, f0.y, acc[i].y);
                acc[i].z = fmaf(r.w, f1.x, acc[i].z);
                acc[i].w = fmaf(r.w, f1.y, acc[i].w);
            }
        }
        // reduce over tap groups (lanes xor 8, xor 16), then lanes 0-7 store
        #pragma unroll
        for (int i = 0; i < 8; i++) {
            float4 a = acc[i];
            a.x += __shfl_xor_sync(0xffffffffu, a.x, 8);
            a.y += __shfl_xor_sync(0xffffffffu, a.y, 8);
            a.z += __shfl_xor_sync(0xffffffffu, a.z, 8);
            a.w += __shfl_xor_sync(0xffffffffu, a.w, 8);
            a.x += __shfl_xor_sync(0xffffffffu, a.x, 16);
            a.y += __shfl_xor_sync(0xffffffffu, a.y, 16);
            a.z += __shfl_xor_sync(0xffffffffu, a.z, 16);
            a.w += __shfl_xor_sync(0xffffffffu, a.w, 16);
            if (lane < 8) {
                float* row = &s_acc[w*8 + i][lane*4];
                row[0] = a.x; row[1] = a.y; row[2] = a.z; row[3] = a.w;
            }
        }
    }
    __syncthreads();

    // -------- Phase 3: conflict-free LDS + coalesced STG.32 --------
    {
        const int w  = tid >> 5;
        const int xl = tid & 31;
        #pragma unroll
        for (int k = 0; k < 8; k++) {
            const int c  = (w*8 + k) >> 2;
            const int yl = (w*8 + k) & 3;
            const float val = s_acc[yl*32 + xl][c];
            out[((size_t)(b*Cn + c) << 18) + z0t*4096 + (y0t + yl)*64 + x0t + xl] = val;
        }
    }
}

// ---------------------------------------------------------------------------
extern "C" void kernel_launch(void* const* d_in, const int* in_sizes, int n_in,
                              void* d_out, int out_size) {
    const float* feat = (const float*)d_in[0];
    const float* R    = (const float*)d_in[1];
    const float* T    = (const float*)d_in[2];
    const float* K    = (const float*)d_in[3];
    const float* root = (const float*)d_in[4];
    float* out = (float*)d_out;

    prep_kernel<<<(Bz*Vn*HWC)/256, 256>>>(feat, R, T, K, root);
    qpack_kernel<<<(Bz*Vn*4096*16)/256, 256>>>();
    sample_kernel<<<Bz*2048, 512>>>(out);
}

// round 6
// speedup vs baseline: 1.0878x; 1.0878x over previous
#include <cuda_runtime.h>
#include <cuda_fp16.h>

#define Bz 2
#define Vn 4
#define Cn 32
#define Hf 64
#define Wf 64
#define Dv 64
#define Pn (Dv*Dv*Dv)
#define HWQ (4096*128)       // halves per view in Q

__device__ __half g_Q[(size_t)Bz*Vn*HWQ];   // [bv][tex][tap4][c32] fp16
__device__ float  g_cam[Bz*Vn][16];

struct Rec { float w; int off; };            // tap weight + quad offset (halves)

// ---------------------------------------------------------------------------
// Fused pack: f [bv][c][y][x] fp32 -> Q [bv][tex][tap][c] fp16.
// Block = (bv, 2-row stripe). Stage 3 rows x 64x x 32c in SMEM as fp16.
// Block 0 also folds camera constants.
// ---------------------------------------------------------------------------
__global__ __launch_bounds__(256) void pack_kernel(
        const float* __restrict__ f,
        const float* __restrict__ R, const float* __restrict__ T,
        const float* __restrict__ K, const float* __restrict__ root) {
    __shared__ __half s_f[3][64][32];
    const int tid = threadIdx.x;
    const int bv  = blockIdx.x >> 5;
    const int y0  = (blockIdx.x & 31) * 2;

    // load rows y0..y0+2 (clamped), coalesced 64-wide along x
    {
        const int x = tid & 63;
        #pragma unroll
        for (int rc = tid >> 6; rc < 96; rc += 4) {
            const int row = rc >> 5;         // 0..2
            const int c   = rc & 31;
            const int gy  = min(y0 + row, 63);
            s_f[row][x][c] = __float2half(f[(((bv*Cn + c)*Hf) + gy)*Wf + x]);
        }
    }

    if (blockIdx.x == 0 && tid < Bz*Vn) {
        int i = tid, b = i / Vn;
        const float* Ri = R + i*9; const float* Ti = T + i*3;
        const float* Ki = K + i*9; const float* rb = root + b*3;
        float* o = g_cam[i];
        #pragma unroll
        for (int r = 0; r < 9; r++) o[r] = Ri[r];
        #pragma unroll
        for (int r = 0; r < 3; r++)
            o[9+r] = Ri[r*3+0]*rb[0] + Ri[r*3+1]*rb[1] + Ri[r*3+2]*rb[2] + Ti[r];
        o[12] = Ki[0]; o[13] = Ki[4]; o[14] = Ki[2]; o[15] = Ki[5];
    }
    __syncthreads();

    // write 2 rows x 64 texels x 4 taps x 32c fp16, 512B contiguous per warp
    #pragma unroll
    for (int k = tid; k < 2048; k += 256) {
        const int q  = k & 3;            // 16B quarter of the 64B texel-tap
        const int t  = (k >> 2) & 3;     // tap
        const int x  = (k >> 4) & 63;
        const int ry = k >> 10;          // 0..1
        const int sx = min(x + (t & 1), 63);
        const int sr = ry + (t >> 1);
        const uint4 u = *reinterpret_cast<const uint4*>(&s_f[sr][sx][q*8]);
        *reinterpret_cast<uint4*>(
            g_Q + ((size_t)bv*HWQ + ((size_t)((y0+ry)*64 + x))*128 + t*32 + q*8)) = u;
    }
}

// ---------------------------------------------------------------------------
// Main kernel. Tile 32(x) x 4(y) x 1(z) = 128 points, 512 threads.
// Phase 1: project 128 pts x 4 views; remap weights to clamped quad base.
// Phase 2: point-outer/view-inner; one LDG.64/warp per point-view
//          (256B contiguous); single float4 acc; shuffle-reduce taps.
// Phase 3: conflict-free scalar LDS + coalesced STG.32.
// ---------------------------------------------------------------------------
__global__ __launch_bounds__(512, 2) void sample_kernel(float* __restrict__ out) {
    __shared__ float s_cam[128];
    __shared__ Rec   s_rec[128][Vn][4];
    __shared__ float s_acc[128][Cn + 1];

    const int tid = threadIdx.x;
    const int bid = blockIdx.x;
    const int b   = bid >> 11;
    const int t   = bid & 2047;
    const int x0t = (t & 1) * 32;
    const int y0t = ((t >> 1) & 15) * 4;
    const int z0t = t >> 5;

    if (tid < 128) s_cam[tid] = reinterpret_cast<const float*>(g_cam)[b*64 + tid];
    __syncthreads();

    // -------- Phase 1 --------
    {
        const int pl = tid >> 2;
        const int v  = tid & 3;
        const int xi = x0t + (pl & 31);
        const int yi = y0t + (pl >> 5);
        const int zi = z0t;

        const float wx = (xi * (1.0f/63.0f) - 0.5f) * 0.2f;
        const float wy = (yi * (1.0f/63.0f) - 0.5f) * 0.2f;
        const float wz = (zi * (1.0f/63.0f) - 0.5f) * 0.2f;

        const float* cam = &s_cam[v*16];
        const float Xc = cam[0]*wx + cam[1]*wy + cam[2]*wz + cam[9];
        const float Yc = cam[3]*wx + cam[4]*wy + cam[5]*wz + cam[10];
        const float Zc = cam[6]*wx + cam[7]*wy + cam[8]*wz + cam[11];
        const float zc = fmaxf(Zc, 1e-5f);

        const float u  = (Xc * cam[12]) / zc + cam[14];
        const float vv = (Yc * cam[13]) / zc + cam[15];
        const float px = u  * (64.0f/255.0f) - 0.5f;
        const float py = vv * (64.0f/255.0f) - 0.5f;

        const float x0f = floorf(px), y0f = floorf(py);
        const float fx1 = px - x0f,   fy1 = py - y0f;
        const float fx0 = 1.0f - fx1, fy0 = 1.0f - fy1;
        const int ix0 = (int)x0f, iy0 = (int)y0f;
        const int ix1 = ix0 + 1,  iy1 = iy0 + 1;

        const float mx0 = (ix0 >= 0 && ix0 < Wf) ? fx0 : 0.0f;
        const float mx1 = (ix1 >= 0 && ix1 < Wf) ? fx1 : 0.0f;
        const float my0 = (iy0 >= 0 && iy0 < Hf) ? fy0 * 0.25f : 0.0f;
        const float my1 = (iy1 >= 0 && iy1 < Hf) ? fy1 * 0.25f : 0.0f;

        const int bx = min(max(ix0, 0), Wf-2);
        const int by = min(max(iy0, 0), Hf-2);
        const float wqx0 = (ix0 == bx)   ? mx0 : ((ix1 == bx)   ? mx1 : 0.0f);
        const float wqx1 = (ix1 == bx+1) ? mx1 : ((ix0 == bx+1) ? mx0 : 0.0f);
        const float wqy0 = (iy0 == by)   ? my0 : ((iy1 == by)   ? my1 : 0.0f);
        const float wqy1 = (iy1 == by+1) ? my1 : ((iy0 == by+1) ? my0 : 0.0f);

        const int off = (by*Wf + bx) * 128;
        s_rec[pl][v][0] = Rec{wqy0*wqx0, off};
        s_rec[pl][v][1] = Rec{wqy0*wqx1, off};
        s_rec[pl][v][2] = Rec{wqy1*wqx0, off};
        s_rec[pl][v][3] = Rec{wqy1*wqx1, off};
    }
    __syncthreads();

    // -------- Phase 2 --------
    {
        const int w    = tid >> 5;
        const int lane = tid & 31;
        const int tap  = lane >> 3;
        const __half* qb = g_Q + (size_t)b*Vn*HWQ + lane*4;

        #pragma unroll
        for (int i = 0; i < 8; i++) {
            const int pl = w*8 + i;
            float4 a = make_float4(0.f, 0.f, 0.f, 0.f);
            #pragma unroll
            for (int v = 0; v < Vn; v++) {
                const Rec r = s_rec[pl][v][tap];
                const uint2 d = *reinterpret_cast<const uint2*>(qb + (size_t)v*HWQ + r.off);
                const float2 f0 = __half22float2(*reinterpret_cast<const __half2*>(&d.x));
                const float2 f1 = __half22float2(*reinterpret_cast<const __half2*>(&d.y));
                a.x = fmaf(r.w, f0.x, a.x);
                a.y = fmaf(r.w, f0.y, a.y);
                a.z = fmaf(r.w, f1.x, a.z);
                a.w = fmaf(r.w, f1.y, a.w);
            }
            a.x += __shfl_xor_sync(0xffffffffu, a.x, 8);
            a.y += __shfl_xor_sync(0xffffffffu, a.y, 8);
            a.z += __shfl_xor_sync(0xffffffffu, a.z, 8);
            a.w += __shfl_xor_sync(0xffffffffu, a.w, 8);
            a.x += __shfl_xor_sync(0xffffffffu, a.x, 16);
            a.y += __shfl_xor_sync(0xffffffffu, a.y, 16);
            a.z += __shfl_xor_sync(0xffffffffu, a.z, 16);
            a.w += __shfl_xor_sync(0xffffffffu, a.w, 16);
            if (lane < 8) {
                float* row = &s_acc[pl][lane*4];
                row[0] = a.x; row[1] = a.y; row[2] = a.z; row[3] = a.w;
            }
        }
    }
    __syncthreads();

    // -------- Phase 3 --------
    {
        const int w  = tid >> 5;
        const int xl = tid & 31;
        #pragma unroll
        for (int k = 0; k < 8; k++) {
            const int c  = (w*8 + k) >> 2;
            const int yl = (w*8 + k) & 3;
            const float val = s_acc[yl*32 + xl][c];
            out[((size_t)(b*Cn + c) << 18) + z0t*4096 + (y0t + yl)*64 + x0t + xl] = val;
        }
    }
}

// ---------------------------------------------------------------------------
extern "C" void kernel_launch(void* const* d_in, const int* in_sizes, int n_in,
                              void* d_out, int out_size) {
    const float* feat = (const float*)d_in[0];
    const float* R    = (const float*)d_in[1];
    const float* T    = (const float*)d_in[2];
    const float* K    = (const float*)d_in[3];
    const float* root = (const float*)d_in[4];
    float* out = (float*)d_out;

    pack_kernel<<<Bz*Vn*32, 256>>>(feat, R, T, K, root);
    sample_kernel<<<Bz*2048, 512>>>(out);
}

// round 7
// speedup vs baseline: 1.1539x; 1.0608x over previous
#include <cuda_runtime.h>
#include <cuda_fp16.h>

#define Bz 2
#define Vn 4
#define Cn 32
#define Hf 64
#define Wf 64
#define Dv 64
#define HWQ (4096*128)       // halves per view in Q

__device__ __half g_Q[(size_t)Bz*Vn*HWQ];   // [bv][tex][tap4][c32] fp16
__device__ float  g_cam[Bz*Vn][16];

struct Rec { unsigned ww; int off; };        // half2(w,w) + quad offset (halves)

// ---------------------------------------------------------------------------
// Fused pack: f [bv][c][y][x] fp32 -> Q [bv][tex][tap][c] fp16.
// Block = (bv, 1-row stripe): read rows y0,y0+1 (clamped), write one Q row.
// ---------------------------------------------------------------------------
__global__ __launch_bounds__(256) void pack_kernel(
        const float* __restrict__ f,
        const float* __restrict__ R, const float* __restrict__ T,
        const float* __restrict__ K, const float* __restrict__ root) {
    __shared__ __half s_f[2][64][32];
    const int tid = threadIdx.x;
    const int bv  = blockIdx.x >> 6;
    const int y0  = blockIdx.x & 63;

    {
        const int x = tid & 63;
        #pragma unroll
        for (int rc = tid >> 6; rc < 64; rc += 4) {
            const int row = rc >> 5;         // 0..1
            const int c   = rc & 31;
            const int gy  = min(y0 + row, 63);
            s_f[row][x][c] = __float2half(f[(((bv*Cn + c)*Hf) + gy)*Wf + x]);
        }
    }

    if (blockIdx.x == 0 && tid < Bz*Vn) {
        int i = tid, b = i / Vn;
        const float* Ri = R + i*9; const float* Ti = T + i*3;
        const float* Ki = K + i*9; const float* rb = root + b*3;
        float* o = g_cam[i];
        #pragma unroll
        for (int r = 0; r < 9; r++) o[r] = Ri[r];
        #pragma unroll
        for (int r = 0; r < 3; r++)
            o[9+r] = Ri[r*3+0]*rb[0] + Ri[r*3+1]*rb[1] + Ri[r*3+2]*rb[2] + Ti[r];
        o[12] = Ki[0]; o[13] = Ki[4]; o[14] = Ki[2]; o[15] = Ki[5];
    }
    __syncthreads();

    #pragma unroll
    for (int k = tid; k < 1024; k += 256) {
        const int q = k & 3;             // 16B quarter
        const int t = (k >> 2) & 3;      // tap
        const int x = (k >> 4) & 63;
        const int sx = min(x + (t & 1), 63);
        const int sr = t >> 1;
        const uint4 u = *reinterpret_cast<const uint4*>(&s_f[sr][sx][q*8]);
        *reinterpret_cast<uint4*>(
            g_Q + ((size_t)bv*HWQ + ((size_t)(y0*64 + x))*128 + t*32 + q*8)) = u;
    }
}

// ---------------------------------------------------------------------------
// Main kernel. Tile 32(x) x 4(y) x 1(z) = 128 points, 512 threads.
// Phase 2: view-outer/point-inner, HFMA2 accumulation, warp-uniform gather
//          skip when consecutive x-points share the texel quad.
// ---------------------------------------------------------------------------
__global__ __launch_bounds__(512, 2) void sample_kernel(float* __restrict__ out) {
    __shared__ float s_cam[128];
    __shared__ Rec   s_rec[128][Vn][4];      // [pl][v][tap]
    __shared__ float s_acc[128][Cn + 1];

    const int tid = threadIdx.x;
    const int bid = blockIdx.x;
    const int b   = bid >> 11;
    const int t   = bid & 2047;
    const int x0t = (t & 1) * 32;
    const int y0t = ((t >> 1) & 15) * 4;
    const int z0t = t >> 5;

    if (tid < 128) s_cam[tid] = reinterpret_cast<const float*>(g_cam)[b*64 + tid];
    __syncthreads();

    // -------- Phase 1: projection + weight remap, half2-packed records ------
    {
        const int pl = tid >> 2;
        const int v  = tid & 3;
        const int xi = x0t + (pl & 31);
        const int yi = y0t + (pl >> 5);
        const int zi = z0t;

        const float wx = (xi * (1.0f/63.0f) - 0.5f) * 0.2f;
        const float wy = (yi * (1.0f/63.0f) - 0.5f) * 0.2f;
        const float wz = (zi * (1.0f/63.0f) - 0.5f) * 0.2f;

        const float* cam = &s_cam[v*16];
        const float Xc = cam[0]*wx + cam[1]*wy + cam[2]*wz + cam[9];
        const float Yc = cam[3]*wx + cam[4]*wy + cam[5]*wz + cam[10];
        const float Zc = cam[6]*wx + cam[7]*wy + cam[8]*wz + cam[11];
        const float zc = fmaxf(Zc, 1e-5f);

        const float u  = (Xc * cam[12]) / zc + cam[14];
        const float vv = (Yc * cam[13]) / zc + cam[15];
        const float px = u  * (64.0f/255.0f) - 0.5f;
        const float py = vv * (64.0f/255.0f) - 0.5f;

        const float x0f = floorf(px), y0f = floorf(py);
        const float fx1 = px - x0f,   fy1 = py - y0f;
        const float fx0 = 1.0f - fx1, fy0 = 1.0f - fy1;
        const int ix0 = (int)x0f, iy0 = (int)y0f;
        const int ix1 = ix0 + 1,  iy1 = iy0 + 1;

        const float mx0 = (ix0 >= 0 && ix0 < Wf) ? fx0 : 0.0f;
        const float mx1 = (ix1 >= 0 && ix1 < Wf) ? fx1 : 0.0f;
        const float my0 = (iy0 >= 0 && iy0 < Hf) ? fy0 * 0.25f : 0.0f;
        const float my1 = (iy1 >= 0 && iy1 < Hf) ? fy1 * 0.25f : 0.0f;

        const int bx = min(max(ix0, 0), Wf-2);
        const int by = min(max(iy0, 0), Hf-2);
        const float wqx0 = (ix0 == bx)   ? mx0 : ((ix1 == bx)   ? mx1 : 0.0f);
        const float wqx1 = (ix1 == bx+1) ? mx1 : ((ix0 == bx+1) ? mx0 : 0.0f);
        const float wqy0 = (iy0 == by)   ? my0 : ((iy1 == by)   ? my1 : 0.0f);
        const float wqy1 = (iy1 == by+1) ? my1 : ((iy0 == by+1) ? my0 : 0.0f);

        const int off = (by*Wf + bx) * 128;
        const float w0 = wqy0*wqx0, w1 = wqy0*wqx1, w2 = wqy1*wqx0, w3 = wqy1*wqx1;
        __half2 h;
        h = __floats2half2_rn(w0, w0); s_rec[pl][v][0] = Rec{*reinterpret_cast<unsigned*>(&h), off};
        h = __floats2half2_rn(w1, w1); s_rec[pl][v][1] = Rec{*reinterpret_cast<unsigned*>(&h), off};
        h = __floats2half2_rn(w2, w2); s_rec[pl][v][2] = Rec{*reinterpret_cast<unsigned*>(&h), off};
        h = __floats2half2_rn(w3, w3); s_rec[pl][v][3] = Rec{*reinterpret_cast<unsigned*>(&h), off};
    }
    __syncthreads();

    // -------- Phase 2: HFMA2 gather-accumulate --------
    {
        const int w    = tid >> 5;
        const int lane = tid & 31;
        const int tap  = lane >> 3;
        const __half* qb = g_Q + (size_t)b*Vn*HWQ + lane*4;

        __half2 a0[8], a1[8];
        const __half2 hz = __floats2half2_rn(0.f, 0.f);
        #pragma unroll
        for (int i = 0; i < 8; i++) { a0[i] = hz; a1[i] = hz; }

        #pragma unroll
        for (int v = 0; v < Vn; v++) {
            const __half* qv = qb + (size_t)v*HWQ;
            int prev = -1;
            uint2 d = make_uint2(0u, 0u);
            #pragma unroll
            for (int i = 0; i < 8; i++) {
                const Rec r = s_rec[w*8 + i][v][tap];
                if (r.off != prev) {                       // warp-uniform branch
                    d = *reinterpret_cast<const uint2*>(qv + r.off);
                    prev = r.off;
                }
                const __half2 ww = *reinterpret_cast<const __half2*>(&r.ww);
                a0[i] = __hfma2(ww, *reinterpret_cast<const __half2*>(&d.x), a0[i]);
                a1[i] = __hfma2(ww, *reinterpret_cast<const __half2*>(&d.y), a1[i]);
            }
        }

        // reduce: xor8 in half2, convert, xor16 in f32; lanes 0-7 store
        #pragma unroll
        for (int i = 0; i < 8; i++) {
            unsigned u0 = *reinterpret_cast<unsigned*>(&a0[i]);
            unsigned u1 = *reinterpret_cast<unsigned*>(&a1[i]);
            unsigned p0 = __shfl_xor_sync(0xffffffffu, u0, 8);
            unsigned p1 = __shfl_xor_sync(0xffffffffu, u1, 8);
            const __half2 s0 = __hadd2(a0[i], *reinterpret_cast<__half2*>(&p0));
            const __half2 s1 = __hadd2(a1[i], *reinterpret_cast<__half2*>(&p1));
            float2 f0 = __half22float2(s0);
            float2 f1 = __half22float2(s1);
            f0.x += __shfl_xor_sync(0xffffffffu, f0.x, 16);
            f0.y += __shfl_xor_sync(0xffffffffu, f0.y, 16);
            f1.x += __shfl_xor_sync(0xffffffffu, f1.x, 16);
            f1.y += __shfl_xor_sync(0xffffffffu, f1.y, 16);
            if (lane < 8) {
                float* row = &s_acc[w*8 + i][lane*4];
                row[0] = f0.x; row[1] = f0.y; row[2] = f1.x; row[3] = f1.y;
            }
        }
    }
    __syncthreads();

    // -------- Phase 3: conflict-free LDS + coalesced STG.32 --------
    {
        const int w  = tid >> 5;
        const int xl = tid & 31;
        #pragma unroll
        for (int k = 0; k < 8; k++) {
            const int c  = (w*8 + k) >> 2;
            const int yl = (w*8 + k) & 3;
            const float val = s_acc[yl*32 + xl][c];
            out[((size_t)(b*Cn + c) << 18) + z0t*4096 + (y0t + yl)*64 + x0t + xl] = val;
        }
    }
}

// ---------------------------------------------------------------------------
extern "C" void kernel_launch(void* const* d_in, const int* in_sizes, int n_in,
                              void* d_out, int out_size) {
    const float* feat = (const float*)d_in[0];
    const float* R    = (const float*)d_in[1];
    const float* T    = (const float*)d_in[2];
    const float* K    = (const float*)d_in[3];
    const float* root = (const float*)d_in[4];
    float* out = (float*)d_out;

    pack_kernel<<<Bz*Vn*64, 256>>>(feat, R, T, K, root);
    sample_kernel<<<Bz*2048, 512>>>(out);
}

// round 8
// speedup vs baseline: 1.2156x; 1.0534x over previous
#include <cuda_runtime.h>
#include <cuda_fp16.h>

#define Bz 2
#define Vn 4
#define Cn 32
#define Hf 64
#define Wf 64
#define Dv 64
#define HWQ (4096*128)       // halves per view in Q

__device__ __half g_Q[(size_t)Bz*Vn*HWQ];   // [bv][tex][tap4][c32] fp16
__device__ float  g_cam[Bz*Vn][16];

struct Rec { unsigned ww; int off; };        // half2(w,w) + quad offset (halves)

// ---------------------------------------------------------------------------
// Fused pack: f [bv][c][y][x] fp32 -> Q [bv][tex][tap][c] fp16.
// ---------------------------------------------------------------------------
__global__ __launch_bounds__(256) void pack_kernel(
        const float* __restrict__ f,
        const float* __restrict__ R, const float* __restrict__ T,
        const float* __restrict__ K, const float* __restrict__ root) {
    __shared__ __half s_f[2][64][32];
    const int tid = threadIdx.x;
    const int bv  = blockIdx.x >> 6;
    const int y0  = blockIdx.x & 63;

    {
        const int x = tid & 63;
        #pragma unroll
        for (int rc = tid >> 6; rc < 64; rc += 4) {
            const int row = rc >> 5;
            const int c   = rc & 31;
            const int gy  = min(y0 + row, 63);
            s_f[row][x][c] = __float2half(f[(((bv*Cn + c)*Hf) + gy)*Wf + x]);
        }
    }

    if (blockIdx.x == 0 && tid < Bz*Vn) {
        int i = tid, b = i / Vn;
        const float* Ri = R + i*9; const float* Ti = T + i*3;
        const float* Ki = K + i*9; const float* rb = root + b*3;
        float* o = g_cam[i];
        #pragma unroll
        for (int r = 0; r < 9; r++) o[r] = Ri[r];
        #pragma unroll
        for (int r = 0; r < 3; r++)
            o[9+r] = Ri[r*3+0]*rb[0] + Ri[r*3+1]*rb[1] + Ri[r*3+2]*rb[2] + Ti[r];
        o[12] = Ki[0]; o[13] = Ki[4]; o[14] = Ki[2]; o[15] = Ki[5];
    }
    __syncthreads();

    #pragma unroll
    for (int k = tid; k < 1024; k += 256) {
        const int q = k & 3;
        const int t = (k >> 2) & 3;
        const int x = (k >> 4) & 63;
        const int sx = min(x + (t & 1), 63);
        const int sr = t >> 1;
        const uint4 u = *reinterpret_cast<const uint4*>(&s_f[sr][sx][q*8]);
        *reinterpret_cast<uint4*>(
            g_Q + ((size_t)bv*HWQ + ((size_t)(y0*64 + x))*128 + t*32 + q*8)) = u;
    }
}

// ---------------------------------------------------------------------------
// Main kernel. Tile 32(x) x 4(y) x 1(z), 512 threads, 3 blocks/SM target.
// Phase 2: 4-point batch outer / view inner; HFMA2; warp-uniform gather skip.
// ---------------------------------------------------------------------------
__global__ __launch_bounds__(512, 3) void sample_kernel(float* __restrict__ out) {
    __shared__ float s_cam[128];
    __shared__ Rec   s_rec[128][Vn][4];
    __shared__ float s_acc[128][Cn + 1];

    const int tid = threadIdx.x;
    const int bid = blockIdx.x;
    const int b   = bid >> 11;
    const int t   = bid & 2047;
    const int x0t = (t & 1) * 32;
    const int y0t = ((t >> 1) & 15) * 4;
    const int z0t = t >> 5;

    if (tid < 128) s_cam[tid] = reinterpret_cast<const float*>(g_cam)[b*64 + tid];
    __syncthreads();

    // -------- Phase 1: projection + weight remap --------
    {
        const int pl = tid >> 2;
        const int v  = tid & 3;
        const int xi = x0t + (pl & 31);
        const int yi = y0t + (pl >> 5);
        const int zi = z0t;

        const float wx = (xi * (1.0f/63.0f) - 0.5f) * 0.2f;
        const float wy = (yi * (1.0f/63.0f) - 0.5f) * 0.2f;
        const float wz = (zi * (1.0f/63.0f) - 0.5f) * 0.2f;

        const float* cam = &s_cam[v*16];
        const float Xc = cam[0]*wx + cam[1]*wy + cam[2]*wz + cam[9];
        const float Yc = cam[3]*wx + cam[4]*wy + cam[5]*wz + cam[10];
        const float Zc = cam[6]*wx + cam[7]*wy + cam[8]*wz + cam[11];
        const float zc = fmaxf(Zc, 1e-5f);

        const float u  = (Xc * cam[12]) / zc + cam[14];
        const float vv = (Yc * cam[13]) / zc + cam[15];
        const float px = u  * (64.0f/255.0f) - 0.5f;
        const float py = vv * (64.0f/255.0f) - 0.5f;

        const float x0f = floorf(px), y0f = floorf(py);
        const float fx1 = px - x0f,   fy1 = py - y0f;
        const float fx0 = 1.0f - fx1, fy0 = 1.0f - fy1;
        const int ix0 = (int)x0f, iy0 = (int)y0f;
        const int ix1 = ix0 + 1,  iy1 = iy0 + 1;

        const float mx0 = (ix0 >= 0 && ix0 < Wf) ? fx0 : 0.0f;
        const float mx1 = (ix1 >= 0 && ix1 < Wf) ? fx1 : 0.0f;
        const float my0 = (iy0 >= 0 && iy0 < Hf) ? fy0 * 0.25f : 0.0f;
        const float my1 = (iy1 >= 0 && iy1 < Hf) ? fy1 * 0.25f : 0.0f;

        const int bx = min(max(ix0, 0), Wf-2);
        const int by = min(max(iy0, 0), Hf-2);
        const float wqx0 = (ix0 == bx)   ? mx0 : ((ix1 == bx)   ? mx1 : 0.0f);
        const float wqx1 = (ix1 == bx+1) ? mx1 : ((ix0 == bx+1) ? mx0 : 0.0f);
        const float wqy0 = (iy0 == by)   ? my0 : ((iy1 == by)   ? my1 : 0.0f);
        const float wqy1 = (iy1 == by+1) ? my1 : ((iy0 == by+1) ? my0 : 0.0f);

        const int off = (by*Wf + bx) * 128;
        const float w0 = wqy0*wqx0, w1 = wqy0*wqx1, w2 = wqy1*wqx0, w3 = wqy1*wqx1;
        __half2 h;
        h = __floats2half2_rn(w0, w0); s_rec[pl][v][0] = Rec{*reinterpret_cast<unsigned*>(&h), off};
        h = __floats2half2_rn(w1, w1); s_rec[pl][v][1] = Rec{*reinterpret_cast<unsigned*>(&h), off};
        h = __floats2half2_rn(w2, w2); s_rec[pl][v][2] = Rec{*reinterpret_cast<unsigned*>(&h), off};
        h = __floats2half2_rn(w3, w3); s_rec[pl][v][3] = Rec{*reinterpret_cast<unsigned*>(&h), off};
    }
    __syncthreads();

    // -------- Phase 2: batch-outer (2x4 pts) / view-inner, HFMA2 --------
    {
        const int w    = tid >> 5;
        const int lane = tid & 31;
        const int tap  = lane >> 3;
        const __half* qb = g_Q + (size_t)b*Vn*HWQ + lane*4;
        const __half2 hz = __floats2half2_rn(0.f, 0.f);

        #pragma unroll
        for (int h2 = 0; h2 < 2; h2++) {
            __half2 a0[4], a1[4];
            #pragma unroll
            for (int i = 0; i < 4; i++) { a0[i] = hz; a1[i] = hz; }

            #pragma unroll
            for (int v = 0; v < Vn; v++) {
                const __half* qv = qb + (size_t)v*HWQ;
                int prev = -1;
                uint2 d = make_uint2(0u, 0u);
                #pragma unroll
                for (int i = 0; i < 4; i++) {
                    const Rec r = s_rec[w*8 + h2*4 + i][v][tap];
                    if (r.off != prev) {                   // warp-uniform branch
                        d = *reinterpret_cast<const uint2*>(qv + r.off);
                        prev = r.off;
                    }
                    const __half2 ww = *reinterpret_cast<const __half2*>(&r.ww);
                    a0[i] = __hfma2(ww, *reinterpret_cast<const __half2*>(&d.x), a0[i]);
                    a1[i] = __hfma2(ww, *reinterpret_cast<const __half2*>(&d.y), a1[i]);
                }
            }

            // reduce: xor8 in half2, convert, xor16 in f32; lanes 0-7 store
            #pragma unroll
            for (int i = 0; i < 4; i++) {
                unsigned u0 = *reinterpret_cast<unsigned*>(&a0[i]);
                unsigned u1 = *reinterpret_cast<unsigned*>(&a1[i]);
                unsigned p0 = __shfl_xor_sync(0xffffffffu, u0, 8);
                unsigned p1 = __shfl_xor_sync(0xffffffffu, u1, 8);
                const __half2 s0 = __hadd2(a0[i], *reinterpret_cast<__half2*>(&p0));
                const __half2 s1 = __hadd2(a1[i], *reinterpret_cast<__half2*>(&p1));
                float2 f0 = __half22float2(s0);
                float2 f1 = __half22float2(s1);
                f0.x += __shfl_xor_sync(0xffffffffu, f0.x, 16);
                f0.y += __shfl_xor_sync(0xffffffffu, f0.y, 16);
                f1.x += __shfl_xor_sync(0xffffffffu, f1.x, 16);
                f1.y += __shfl_xor_sync(0xffffffffu, f1.y, 16);
                if (lane < 8) {
                    float* row = &s_acc[w*8 + h2*4 + i][lane*4];
                    row[0] = f0.x; row[1] = f0.y; row[2] = f1.x; row[3] = f1.y;
                }
            }
        }
    }
    __syncthreads();

    // -------- Phase 3: conflict-free LDS + coalesced STG.32 --------
    {
        const int w  = tid >> 5;
        const int xl = tid & 31;
        #pragma unroll
        for (int k = 0; k < 8; k++) {
            const int c  = (w*8 + k) >> 2;
            const int yl = (w*8 + k) & 3;
            const float val = s_acc[yl*32 + xl][c];
            out[((size_t)(b*Cn + c) << 18) + z0t*4096 + (y0t + yl)*64 + x0t + xl] = val;
        }
    }
}

// ---------------------------------------------------------------------------
extern "C" void kernel_launch(void* const* d_in, const int* in_sizes, int n_in,
                              void* d_out, int out_size) {
    const float* feat = (const float*)d_in[0];
    const float* R    = (const float*)d_in[1];
    const float* T    = (const float*)d_in[2];
    const float* K    = (const float*)d_in[3];
    const float* root = (const float*)d_in[4];
    float* out = (float*)d_out;

    pack_kernel<<<Bz*Vn*64, 256>>>(feat, R, T, K, root);
    sample_kernel<<<Bz*2048, 512>>>(out);
}

// round 9
// speedup vs baseline: 1.3582x; 1.1173x over previous
#include <cuda_runtime.h>
#include <cuda_fp16.h>

#define Bz 2
#define Vn 4
#define Cn 32
#define Hf 64
#define Wf 64
#define Dv 64
#define QV 65536            // uint4 (16B) units per view: 4096 texels x 16 chpairs

// Q layout: [bv][tex][chpair(16)][tap(4)][ch(2)] fp16 -> one uint4 = 4 taps x 2 ch
__device__ uint4 g_Q[Bz*Vn*QV];              // 8 MB
__device__ float g_cam[Bz*Vn][16];

// ---------------------------------------------------------------------------
// Pack: f [bv][c][y][x] fp32 -> g_Q. Block = (bv, y-row). Reads rows y, y+1.
// ---------------------------------------------------------------------------
__global__ __launch_bounds__(256) void pack_kernel(
        const float* __restrict__ f,
        const float* __restrict__ R, const float* __restrict__ T,
        const float* __restrict__ K, const float* __restrict__ root) {
    __shared__ __half s_f[2][64][32];
    const int tid = threadIdx.x;
    const int bv  = blockIdx.x >> 6;
    const int y0  = blockIdx.x & 63;

    #pragma unroll
    for (int i = 0; i < 4; i++) {
        const int id  = tid + i*256;         // 1024 float4 reads
        const int x4  = (id & 15) * 4;
        const int c   = (id >> 4) & 31;
        const int row = id >> 9;             // 0..1
        const int gy  = min(y0 + row, 63);
        const float4 a = __ldg(reinterpret_cast<const float4*>(
            &f[(((bv*Cn + c)*Hf) + gy)*Wf + x4]));
        s_f[row][x4+0][c] = __float2half(a.x);
        s_f[row][x4+1][c] = __float2half(a.y);
        s_f[row][x4+2][c] = __float2half(a.z);
        s_f[row][x4+3][c] = __float2half(a.w);
    }

    if (blockIdx.x == 0 && tid < Bz*Vn) {
        int i = tid, b = i / Vn;
        const float* Ri = R + i*9; const float* Ti = T + i*3;
        const float* Ki = K + i*9; const float* rb = root + b*3;
        float* o = g_cam[i];
        #pragma unroll
        for (int r = 0; r < 9; r++) o[r] = Ri[r];
        #pragma unroll
        for (int r = 0; r < 3; r++)
            o[9+r] = Ri[r*3+0]*rb[0] + Ri[r*3+1]*rb[1] + Ri[r*3+2]*rb[2] + Ti[r];
        o[12] = Ki[0]; o[13] = Ki[4]; o[14] = Ki[2]; o[15] = Ki[5];
    }
    __syncthreads();

    #pragma unroll
    for (int i = 0; i < 4; i++) {
        const int k = tid + i*256;           // 1024 items: 64 tex x 16 chpairs
        const int q = k & 15;
        const int x = k >> 4;
        const int x1 = min(x + 1, 63);
        uint4 u;                             // taps: (x,y0),(x1,y0),(x,y0+1),(x1,y0+1)
        u.x = *reinterpret_cast<const unsigned*>(&s_f[0][x ][2*q]);
        u.y = *reinterpret_cast<const unsigned*>(&s_f[0][x1][2*q]);
        u.z = *reinterpret_cast<const unsigned*>(&s_f[1][x ][2*q]);
        u.w = *reinterpret_cast<const unsigned*>(&s_f[1][x1][2*q]);
        g_Q[bv*QV + (y0*64 + x)*16 + q] = u;
    }
}

// ---------------------------------------------------------------------------
// Main kernel. Tile 32(x) x 4(y) x 1(z), 512 threads, 3 blocks/SM.
// Phase 2: 16 lanes per point (lane = ch-pair); LDG.128 = all 4 taps x 2 ch;
//          warp = 2 points per gather; HFMA2 chains; NO cross-lane reduction.
// ---------------------------------------------------------------------------
__global__ __launch_bounds__(512, 3) void sample_kernel(float* __restrict__ out) {
    __shared__ float s_cam[128];
    __shared__ uint4 s_ww[128][Vn];          // 4 x half2(w,w) per (pl, v)
    __shared__ int   s_off[128][Vn];         // quad offset (uint4 units)
    __shared__ float s_acc[128][Cn + 1];

    const int tid = threadIdx.x;
    const int bid = blockIdx.x;
    const int b   = bid >> 11;
    const int t   = bid & 2047;
    const int x0t = (t & 1) * 32;
    const int y0t = ((t >> 1) & 15) * 4;
    const int z0t = t >> 5;

    if (tid < 128) s_cam[tid] = reinterpret_cast<const float*>(g_cam)[b*64 + tid];
    __syncthreads();

    // -------- Phase 1: projection + weight remap --------
    {
        const int pl = tid >> 2;
        const int v  = tid & 3;
        const int xi = x0t + (pl & 31);
        const int yi = y0t + (pl >> 5);
        const int zi = z0t;

        const float wx = (xi * (1.0f/63.0f) - 0.5f) * 0.2f;
        const float wy = (yi * (1.0f/63.0f) - 0.5f) * 0.2f;
        const float wz = (zi * (1.0f/63.0f) - 0.5f) * 0.2f;

        const float* cam = &s_cam[v*16];
        const float Xc = cam[0]*wx + cam[1]*wy + cam[2]*wz + cam[9];
        const float Yc = cam[3]*wx + cam[4]*wy + cam[5]*wz + cam[10];
        const float Zc = cam[6]*wx + cam[7]*wy + cam[8]*wz + cam[11];
        const float zc = fmaxf(Zc, 1e-5f);

        const float u  = (Xc * cam[12]) / zc + cam[14];
        const float vv = (Yc * cam[13]) / zc + cam[15];
        const float px = u  * (64.0f/255.0f) - 0.5f;
        const float py = vv * (64.0f/255.0f) - 0.5f;

        const float x0f = floorf(px), y0f = floorf(py);
        const float fx1 = px - x0f,   fy1 = py - y0f;
        const float fx0 = 1.0f - fx1, fy0 = 1.0f - fy1;
        const int ix0 = (int)x0f, iy0 = (int)y0f;
        const int ix1 = ix0 + 1,  iy1 = iy0 + 1;

        const float mx0 = (ix0 >= 0 && ix0 < Wf) ? fx0 : 0.0f;
        const float mx1 = (ix1 >= 0 && ix1 < Wf) ? fx1 : 0.0f;
        const float my0 = (iy0 >= 0 && iy0 < Hf) ? fy0 * 0.25f : 0.0f;
        const float my1 = (iy1 >= 0 && iy1 < Hf) ? fy1 * 0.25f : 0.0f;

        const int bx = min(max(ix0, 0), Wf-2);
        const int by = min(max(iy0, 0), Hf-2);
        const float wqx0 = (ix0 == bx)   ? mx0 : ((ix1 == bx)   ? mx1 : 0.0f);
        const float wqx1 = (ix1 == bx+1) ? mx1 : ((ix0 == bx+1) ? mx0 : 0.0f);
        const float wqy0 = (iy0 == by)   ? my0 : ((iy1 == by)   ? my1 : 0.0f);
        const float wqy1 = (iy1 == by+1) ? my1 : ((iy0 == by+1) ? my0 : 0.0f);

        const float w0 = wqy0*wqx0, w1 = wqy0*wqx1, w2 = wqy1*wqx0, w3 = wqy1*wqx1;
        __half2 h0 = __floats2half2_rn(w0, w0);
        __half2 h1 = __floats2half2_rn(w1, w1);
        __half2 h2 = __floats2half2_rn(w2, w2);
        __half2 h3 = __floats2half2_rn(w3, w3);
        uint4 u4;
        u4.x = *reinterpret_cast<unsigned*>(&h0);
        u4.y = *reinterpret_cast<unsigned*>(&h1);
        u4.z = *reinterpret_cast<unsigned*>(&h2);
        u4.w = *reinterpret_cast<unsigned*>(&h3);
        s_ww[pl][v]  = u4;
        s_off[pl][v] = (by*Wf + bx) * 16;    // uint4 units
    }
    __syncthreads();

    // -------- Phase 2: tap-major gather, no reduction --------
    {
        const int w    = tid >> 5;
        const int lane = tid & 31;
        const int h    = lane >> 4;          // point within pair
        const int q    = lane & 15;          // channel pair
        const uint4* qv0 = g_Q + (size_t)(b*Vn)*QV + q;
        const __half2 hz = __floats2half2_rn(0.f, 0.f);

        __half2 acc[4][2];                   // [pair][even/odd view chain]
        #pragma unroll
        for (int pr = 0; pr < 4; pr++) { acc[pr][0] = hz; acc[pr][1] = hz; }

        #pragma unroll
        for (int v = 0; v < Vn; v++) {
            const uint4* qv = qv0 + v*QV;
            int prev = -1;
            uint4 d = make_uint4(0u,0u,0u,0u);
            #pragma unroll
            for (int pr = 0; pr < 4; pr++) {
                const int pl = w*8 + pr*2 + h;
                const uint4 ww = s_ww[pl][v];
                const int  off = s_off[pl][v];
                const unsigned chg = __ballot_sync(0xffffffffu, off != prev);
                if (chg) d = __ldg(qv + off);
                prev = off;
                const int cc = v & 1;
                acc[pr][cc] = __hfma2(*reinterpret_cast<const __half2*>(&ww.x),
                                      *reinterpret_cast<const __half2*>(&d.x), acc[pr][cc]);
                acc[pr][cc] = __hfma2(*reinterpret_cast<const __half2*>(&ww.y),
                                      *reinterpret_cast<const __half2*>(&d.y), acc[pr][cc]);
                acc[pr][cc] = __hfma2(*reinterpret_cast<const __half2*>(&ww.z),
                                      *reinterpret_cast<const __half2*>(&d.z), acc[pr][cc]);
                acc[pr][cc] = __hfma2(*reinterpret_cast<const __half2*>(&ww.w),
                                      *reinterpret_cast<const __half2*>(&d.w), acc[pr][cc]);
            }
        }

        #pragma unroll
        for (int pr = 0; pr < 4; pr++) {
            const int pl = w*8 + pr*2 + h;
            const __half2 s = __hadd2(acc[pr][0], acc[pr][1]);
            const float2 fo = __half22float2(s);
            s_acc[pl][2*q    ] = fo.x;
            s_acc[pl][2*q + 1] = fo.y;
        }
    }
    __syncthreads();

    // -------- Phase 3: conflict-free LDS + coalesced STG.32 --------
    {
        const int w  = tid >> 5;
        const int xl = tid & 31;
        #pragma unroll
        for (int k = 0; k < 8; k++) {
            const int c  = (w*8 + k) >> 2;
            const int yl = (w*8 + k) & 3;
            const float val = s_acc[yl*32 + xl][c];
            out[((size_t)(b*Cn + c) << 18) + z0t*4096 + (y0t + yl)*64 + x0t + xl] = val;
        }
    }
}

// ---------------------------------------------------------------------------
extern "C" void kernel_launch(void* const* d_in, const int* in_sizes, int n_in,
                              void* d_out, int out_size) {
    const float* feat = (const float*)d_in[0];
    const float* R    = (const float*)d_in[1];
    const float* T    = (const float*)d_in[2];
    const float* K    = (const float*)d_in[3];
    const float* root = (const float*)d_in[4];
    float* out = (float*)d_out;

    pack_kernel<<<Bz*Vn*64, 256>>>(feat, R, T, K, root);
    sample_kernel<<<Bz*2048, 512>>>(out);
}

// round 10
// speedup vs baseline: 1.5123x; 1.1135x over previous
#include <cuda_runtime.h>
#include <cuda_fp16.h>

#define Bz 2
#define Vn 4
#define Cn 32
#define Hf 64
#define Wf 64
#define Dv 64
#define QV 65536            // uint4 (16B) units per view: 4096 texels x 16 chpairs

// Q layout: [bv][tex][chpair(16)][tap(4)][ch(2)] fp16 -> one uint4 = 4 taps x 2 ch
__device__ uint4 g_Q[Bz*Vn*QV];              // 8 MB
__device__ float g_cam[Bz*Vn][16];

// ---------------------------------------------------------------------------
// Pack: f [bv][c][y][x] fp32 -> g_Q. Block = (bv, y-row). Reads rows y, y+1.
// ---------------------------------------------------------------------------
__global__ __launch_bounds__(256) void pack_kernel(
        const float* __restrict__ f,
        const float* __restrict__ R, const float* __restrict__ T,
        const float* __restrict__ K, const float* __restrict__ root) {
    __shared__ __half s_f[2][64][32];
    const int tid = threadIdx.x;
    const int bv  = blockIdx.x >> 6;
    const int y0  = blockIdx.x & 63;

    #pragma unroll
    for (int i = 0; i < 4; i++) {
        const int id  = tid + i*256;
        const int x4  = (id & 15) * 4;
        const int c   = (id >> 4) & 31;
        const int row = id >> 9;
        const int gy  = min(y0 + row, 63);
        const float4 a = __ldg(reinterpret_cast<const float4*>(
            &f[(((bv*Cn + c)*Hf) + gy)*Wf + x4]));
        s_f[row][x4+0][c] = __float2half(a.x);
        s_f[row][x4+1][c] = __float2half(a.y);
        s_f[row][x4+2][c] = __float2half(a.z);
        s_f[row][x4+3][c] = __float2half(a.w);
    }

    if (blockIdx.x == 0 && tid < Bz*Vn) {
        int i = tid, b = i / Vn;
        const float* Ri = R + i*9; const float* Ti = T + i*3;
        const float* Ki = K + i*9; const float* rb = root + b*3;
        float* o = g_cam[i];
        #pragma unroll
        for (int r = 0; r < 9; r++) o[r] = Ri[r];
        #pragma unroll
        for (int r = 0; r < 3; r++)
            o[9+r] = Ri[r*3+0]*rb[0] + Ri[r*3+1]*rb[1] + Ri[r*3+2]*rb[2] + Ti[r];
        o[12] = Ki[0]; o[13] = Ki[4]; o[14] = Ki[2]; o[15] = Ki[5];
    }
    __syncthreads();

    #pragma unroll
    for (int i = 0; i < 4; i++) {
        const int k = tid + i*256;           // 1024 items: 64 tex x 16 chpairs
        const int q = k & 15;
        const int x = k >> 4;
        const int x1 = min(x + 1, 63);
        uint4 u;                             // taps: (x,y0),(x1,y0),(x,y0+1),(x1,y0+1)
        u.x = *reinterpret_cast<const unsigned*>(&s_f[0][x ][2*q]);
        u.y = *reinterpret_cast<const unsigned*>(&s_f[0][x1][2*q]);
        u.z = *reinterpret_cast<const unsigned*>(&s_f[1][x ][2*q]);
        u.w = *reinterpret_cast<const unsigned*>(&s_f[1][x1][2*q]);
        g_Q[bv*QV + (y0*64 + x)*16 + q] = u;
    }
}

// ---------------------------------------------------------------------------
// Main kernel. Tile 32(x) x 4(y) x 1(z), 512 threads, 3 blocks/SM.
// Phase 2: 16 lanes per point (lane = ch-pair); per point: one LDS.128 gets
//          all 4 view offsets, 4 LDG.128 issued back-to-back (MLP=4), then
//          16 HFMA2. No ballot, no dedup, no cross-lane reduction.
// ---------------------------------------------------------------------------
__global__ __launch_bounds__(512, 3) void sample_kernel(float* __restrict__ out) {
    __shared__ float s_cam[128];
    __shared__ uint4 s_ww[128][Vn];          // 4 x half2(w,w) per (pl, v)
    __shared__ int4  s_off4[128];            // per point: offsets for 4 views
    __shared__ float s_acc[128][Cn + 1];

    const int tid = threadIdx.x;
    const int bid = blockIdx.x;
    const int b   = bid >> 11;
    const int t   = bid & 2047;
    const int x0t = (t & 1) * 32;
    const int y0t = ((t >> 1) & 15) * 4;
    const int z0t = t >> 5;

    if (tid < 128) s_cam[tid] = reinterpret_cast<const float*>(g_cam)[b*64 + tid];
    __syncthreads();

    // -------- Phase 1: projection + weight remap --------
    {
        const int pl = tid >> 2;
        const int v  = tid & 3;
        const int xi = x0t + (pl & 31);
        const int yi = y0t + (pl >> 5);
        const int zi = z0t;

        const float wx = (xi * (1.0f/63.0f) - 0.5f) * 0.2f;
        const float wy = (yi * (1.0f/63.0f) - 0.5f) * 0.2f;
        const float wz = (zi * (1.0f/63.0f) - 0.5f) * 0.2f;

        const float* cam = &s_cam[v*16];
        const float Xc = cam[0]*wx + cam[1]*wy + cam[2]*wz + cam[9];
        const float Yc = cam[3]*wx + cam[4]*wy + cam[5]*wz + cam[10];
        const float Zc = cam[6]*wx + cam[7]*wy + cam[8]*wz + cam[11];
        const float zc = fmaxf(Zc, 1e-5f);

        const float u  = (Xc * cam[12]) / zc + cam[14];
        const float vv = (Yc * cam[13]) / zc + cam[15];
        const float px = u  * (64.0f/255.0f) - 0.5f;
        const float py = vv * (64.0f/255.0f) - 0.5f;

        const float x0f = floorf(px), y0f = floorf(py);
        const float fx1 = px - x0f,   fy1 = py - y0f;
        const float fx0 = 1.0f - fx1, fy0 = 1.0f - fy1;
        const int ix0 = (int)x0f, iy0 = (int)y0f;
        const int ix1 = ix0 + 1,  iy1 = iy0 + 1;

        const float mx0 = (ix0 >= 0 && ix0 < Wf) ? fx0 : 0.0f;
        const float mx1 = (ix1 >= 0 && ix1 < Wf) ? fx1 : 0.0f;
        const float my0 = (iy0 >= 0 && iy0 < Hf) ? fy0 * 0.25f : 0.0f;
        const float my1 = (iy1 >= 0 && iy1 < Hf) ? fy1 * 0.25f : 0.0f;

        const int bx = min(max(ix0, 0), Wf-2);
        const int by = min(max(iy0, 0), Hf-2);
        const float wqx0 = (ix0 == bx)   ? mx0 : ((ix1 == bx)   ? mx1 : 0.0f);
        const float wqx1 = (ix1 == bx+1) ? mx1 : ((ix0 == bx+1) ? mx0 : 0.0f);
        const float wqy0 = (iy0 == by)   ? my0 : ((iy1 == by)   ? my1 : 0.0f);
        const float wqy1 = (iy1 == by+1) ? my1 : ((iy0 == by+1) ? my0 : 0.0f);

        const float w0 = wqy0*wqx0, w1 = wqy0*wqx1, w2 = wqy1*wqx0, w3 = wqy1*wqx1;
        __half2 h0 = __floats2half2_rn(w0, w0);
        __half2 h1 = __floats2half2_rn(w1, w1);
        __half2 h2 = __floats2half2_rn(w2, w2);
        __half2 h3 = __floats2half2_rn(w3, w3);
        uint4 u4;
        u4.x = *reinterpret_cast<unsigned*>(&h0);
        u4.y = *reinterpret_cast<unsigned*>(&h1);
        u4.z = *reinterpret_cast<unsigned*>(&h2);
        u4.w = *reinterpret_cast<unsigned*>(&h3);
        s_ww[pl][v] = u4;
        reinterpret_cast<int*>(&s_off4[pl])[v] = (by*Wf + bx) * 16;   // uint4 units
    }
    __syncthreads();

    // -------- Phase 2: MLP-4 gather, no reduction --------
    {
        const int w    = tid >> 5;
        const int lane = tid & 31;
        const int h    = lane >> 4;          // point within pair
        const int q    = lane & 15;          // channel pair
        const uint4* qb = g_Q + (size_t)(b*Vn)*QV + q;

        #pragma unroll
        for (int pr = 0; pr < 4; pr++) {
            const int pl = w*8 + pr*2 + h;
            const int4 offs = s_off4[pl];            // all 4 view offsets
            const uint4 d0 = __ldg(qb + 0*QV + offs.x);
            const uint4 d1 = __ldg(qb + 1*QV + offs.y);
            const uint4 d2 = __ldg(qb + 2*QV + offs.z);
            const uint4 d3 = __ldg(qb + 3*QV + offs.w);

            __half2 aE = __floats2half2_rn(0.f, 0.f);
            __half2 aO = __floats2half2_rn(0.f, 0.f);
            {
                const uint4 ww = s_ww[pl][0];
                aE = __hfma2(*reinterpret_cast<const __half2*>(&ww.x), *reinterpret_cast<const __half2*>(&d0.x), aE);
                aE = __hfma2(*reinterpret_cast<const __half2*>(&ww.y), *reinterpret_cast<const __half2*>(&d0.y), aE);
                aE = __hfma2(*reinterpret_cast<const __half2*>(&ww.z), *reinterpret_cast<const __half2*>(&d0.z), aE);
                aE = __hfma2(*reinterpret_cast<const __half2*>(&ww.w), *reinterpret_cast<const __half2*>(&d0.w), aE);
            }
            {
                const uint4 ww = s_ww[pl][1];
                aO = __hfma2(*reinterpret_cast<const __half2*>(&ww.x), *reinterpret_cast<const __half2*>(&d1.x), aO);
                aO = __hfma2(*reinterpret_cast<const __half2*>(&ww.y), *reinterpret_cast<const __half2*>(&d1.y), aO);
                aO = __hfma2(*reinterpret_cast<const __half2*>(&ww.z), *reinterpret_cast<const __half2*>(&d1.z), aO);
                aO = __hfma2(*reinterpret_cast<const __half2*>(&ww.w), *reinterpret_cast<const __half2*>(&d1.w), aO);
            }
            {
                const uint4 ww = s_ww[pl][2];
                aE = __hfma2(*reinterpret_cast<const __half2*>(&ww.x), *reinterpret_cast<const __half2*>(&d2.x), aE);
                aE = __hfma2(*reinterpret_cast<const __half2*>(&ww.y), *reinterpret_cast<const __half2*>(&d2.y), aE);
                aE = __hfma2(*reinterpret_cast<const __half2*>(&ww.z), *reinterpret_cast<const __half2*>(&d2.z), aE);
                aE = __hfma2(*reinterpret_cast<const __half2*>(&ww.w), *reinterpret_cast<const __half2*>(&d2.w), aE);
            }
            {
                const uint4 ww = s_ww[pl][3];
                aO = __hfma2(*reinterpret_cast<const __half2*>(&ww.x), *reinterpret_cast<const __half2*>(&d3.x), aO);
                aO = __hfma2(*reinterpret_cast<const __half2*>(&ww.y), *reinterpret_cast<const __half2*>(&d3.y), aO);
                aO = __hfma2(*reinterpret_cast<const __half2*>(&ww.z), *reinterpret_cast<const __half2*>(&d3.z), aO);
                aO = __hfma2(*reinterpret_cast<const __half2*>(&ww.w), *reinterpret_cast<const __half2*>(&d3.w), aO);
            }
            const __half2 s = __hadd2(aE, aO);
            const float2 fo = __half22float2(s);
            s_acc[pl][2*q    ] = fo.x;      // h splits bank parity -> conflict-free
            s_acc[pl][2*q + 1] = fo.y;
        }
    }
    __syncthreads();

    // -------- Phase 3: conflict-free LDS + coalesced STG.32 --------
    {
        const int w  = tid >> 5;
        const int xl = tid & 31;
        #pragma unroll
        for (int k = 0; k < 8; k++) {
            const int c  = (w*8 + k) >> 2;
            const int yl = (w*8 + k) & 3;
            const float val = s_acc[yl*32 + xl][c];
            out[((size_t)(b*Cn + c) << 18) + z0t*4096 + (y0t + yl)*64 + x0t + xl] = val;
        }
    }
}

// ---------------------------------------------------------------------------
extern "C" void kernel_launch(void* const* d_in, const int* in_sizes, int n_in,
                              void* d_out, int out_size) {
    const float* feat = (const float*)d_in[0];
    const float* R    = (const float*)d_in[1];
    const float* T    = (const float*)d_in[2];
    const float* K    = (const float*)d_in[3];
    const float* root = (const float*)d_in[4];
    float* out = (float*)d_out;

    pack_kernel<<<Bz*Vn*64, 256>>>(feat, R, T, K, root);
    sample_kernel<<<Bz*2048, 512>>>(out);
}

// round 11
// speedup vs baseline: 1.6330x; 1.0798x over previous
#include <cuda_runtime.h>
#include <cuda_fp16.h>

#define Bz 2
#define Vn 4
#define Cn 32
#define Hf 64
#define Wf 64
#define Dv 64
#define QV 65536            // uint4 (16B) units per view: 4096 texels x 16 chpairs

// Q layout: [bv][tex][chpair(16)][tap(4)][ch(2)] fp16; texel record = 256B
__device__ uint4 g_Q[Bz*Vn*QV];              // 8 MB
__device__ float g_cam[Bz*Vn][16];

// ---------------------------------------------------------------------------
// Pack: f [bv][c][y][x] fp32 -> g_Q. Block = (bv, y-row), 512 threads.
// ---------------------------------------------------------------------------
__global__ __launch_bounds__(512) void pack_kernel(
        const float* __restrict__ f,
        const float* __restrict__ R, const float* __restrict__ T,
        const float* __restrict__ K, const float* __restrict__ root) {
    __shared__ __half s_f[2][64][32];
    const int tid = threadIdx.x;
    const int bv  = blockIdx.x >> 6;
    const int y0  = blockIdx.x & 63;

    #pragma unroll
    for (int i = 0; i < 2; i++) {
        const int id  = tid + i*512;         // 1024 float4 reads
        const int x4  = (id & 15) * 4;
        const int c   = (id >> 4) & 31;
        const int row = id >> 9;
        const int gy  = min(y0 + row, 63);
        const float4 a = __ldg(reinterpret_cast<const float4*>(
            &f[(((bv*Cn + c)*Hf) + gy)*Wf + x4]));
        s_f[row][x4+0][c] = __float2half(a.x);
        s_f[row][x4+1][c] = __float2half(a.y);
        s_f[row][x4+2][c] = __float2half(a.z);
        s_f[row][x4+3][c] = __float2half(a.w);
    }

    if (blockIdx.x == 0 && tid < Bz*Vn) {
        int i = tid, b = i / Vn;
        const float* Ri = R + i*9; const float* Ti = T + i*3;
        const float* Ki = K + i*9; const float* rb = root + b*3;
        float* o = g_cam[i];
        #pragma unroll
        for (int r = 0; r < 9; r++) o[r] = Ri[r];
        #pragma unroll
        for (int r = 0; r < 3; r++)
            o[9+r] = Ri[r*3+0]*rb[0] + Ri[r*3+1]*rb[1] + Ri[r*3+2]*rb[2] + Ti[r];
        o[12] = Ki[0]; o[13] = Ki[4]; o[14] = Ki[2]; o[15] = Ki[5];
    }
    __syncthreads();

    #pragma unroll
    for (int i = 0; i < 2; i++) {
        const int k = tid + i*512;           // 1024 items: 64 tex x 16 chpairs
        const int q = k & 15;
        const int x = k >> 4;
        const int x1 = min(x + 1, 63);
        uint4 u;                             // taps: (x,y0),(x1,y0),(x,y0+1),(x1,y0+1)
        u.x = *reinterpret_cast<const unsigned*>(&s_f[0][x ][2*q]);
        u.y = *reinterpret_cast<const unsigned*>(&s_f[0][x1][2*q]);
        u.z = *reinterpret_cast<const unsigned*>(&s_f[1][x ][2*q]);
        u.w = *reinterpret_cast<const unsigned*>(&s_f[1][x1][2*q]);
        g_Q[bv*QV + (y0*64 + x)*16 + q] = u;
    }
}

#define FMA4(acc, ww, d)                                                              \
    acc = __hfma2(*reinterpret_cast<const __half2*>(&(ww).x),                         \
                  *reinterpret_cast<const __half2*>(&(d).x), acc);                    \
    acc = __hfma2(*reinterpret_cast<const __half2*>(&(ww).y),                         \
                  *reinterpret_cast<const __half2*>(&(d).y), acc);                    \
    acc = __hfma2(*reinterpret_cast<const __half2*>(&(ww).z),                         \
                  *reinterpret_cast<const __half2*>(&(d).z), acc);                    \
    acc = __hfma2(*reinterpret_cast<const __half2*>(&(ww).w),                         \
                  *reinterpret_cast<const __half2*>(&(d).w), acc);

// ---------------------------------------------------------------------------
// Main kernel. Tile 32(x) x 4(y) x 1(z), 512 threads, 3 blocks/SM.
// Phase 2: lane = (point p0..3, chpair-half q0..7); one LDG.128 carries the
//          same half of 4 x-adjacent points' records -> coalescer dedups
//          shared texel quads (~2 lines/LDG). MLP=4, HFMA2, no reduction.
// ---------------------------------------------------------------------------
__global__ __launch_bounds__(512, 3) void sample_kernel(float* __restrict__ out) {
    __shared__ float s_cam[128];
    __shared__ uint4 s_ww[128][Vn];          // 4 x half2(w,w) per (pl, v)
    __shared__ int4  s_off4[128];            // per point: offsets for 4 views
    __shared__ float s_acc[128][Cn + 1];

    const int tid = threadIdx.x;
    const int bid = blockIdx.x;
    const int b   = bid >> 11;
    const int t   = bid & 2047;
    const int x0t = (t & 1) * 32;
    const int y0t = ((t >> 1) & 15) * 4;
    const int z0t = t >> 5;

    if (tid < 128) s_cam[tid] = reinterpret_cast<const float*>(g_cam)[b*64 + tid];
    __syncthreads();

    // -------- Phase 1: projection + weight remap --------
    {
        const int pl = tid >> 2;
        const int v  = tid & 3;
        const int xi = x0t + (pl & 31);
        const int yi = y0t + (pl >> 5);
        const int zi = z0t;

        const float wx = (xi * (1.0f/63.0f) - 0.5f) * 0.2f;
        const float wy = (yi * (1.0f/63.0f) - 0.5f) * 0.2f;
        const float wz = (zi * (1.0f/63.0f) - 0.5f) * 0.2f;

        const float* cam = &s_cam[v*16];
        const float Xc = cam[0]*wx + cam[1]*wy + cam[2]*wz + cam[9];
        const float Yc = cam[3]*wx + cam[4]*wy + cam[5]*wz + cam[10];
        const float Zc = cam[6]*wx + cam[7]*wy + cam[8]*wz + cam[11];
        const float zc = fmaxf(Zc, 1e-5f);

        const float u  = (Xc * cam[12]) / zc + cam[14];
        const float vv = (Yc * cam[13]) / zc + cam[15];
        const float px = u  * (64.0f/255.0f) - 0.5f;
        const float py = vv * (64.0f/255.0f) - 0.5f;

        const float x0f = floorf(px), y0f = floorf(py);
        const float fx1 = px - x0f,   fy1 = py - y0f;
        const float fx0 = 1.0f - fx1, fy0 = 1.0f - fy1;
        const int ix0 = (int)x0f, iy0 = (int)y0f;
        const int ix1 = ix0 + 1,  iy1 = iy0 + 1;

        const float mx0 = (ix0 >= 0 && ix0 < Wf) ? fx0 : 0.0f;
        const float mx1 = (ix1 >= 0 && ix1 < Wf) ? fx1 : 0.0f;
        const float my0 = (iy0 >= 0 && iy0 < Hf) ? fy0 * 0.25f : 0.0f;
        const float my1 = (iy1 >= 0 && iy1 < Hf) ? fy1 * 0.25f : 0.0f;

        const int bx = min(max(ix0, 0), Wf-2);
        const int by = min(max(iy0, 0), Hf-2);
        const float wqx0 = (ix0 == bx)   ? mx0 : ((ix1 == bx)   ? mx1 : 0.0f);
        const float wqx1 = (ix1 == bx+1) ? mx1 : ((ix0 == bx+1) ? mx0 : 0.0f);
        const float wqy0 = (iy0 == by)   ? my0 : ((iy1 == by)   ? my1 : 0.0f);
        const float wqy1 = (iy1 == by+1) ? my1 : ((iy0 == by+1) ? my0 : 0.0f);

        const float w0 = wqy0*wqx0, w1 = wqy0*wqx1, w2 = wqy1*wqx0, w3 = wqy1*wqx1;
        __half2 h0 = __floats2half2_rn(w0, w0);
        __half2 h1 = __floats2half2_rn(w1, w1);
        __half2 h2 = __floats2half2_rn(w2, w2);
        __half2 h3 = __floats2half2_rn(w3, w3);
        uint4 u4;
        u4.x = *reinterpret_cast<unsigned*>(&h0);
        u4.y = *reinterpret_cast<unsigned*>(&h1);
        u4.z = *reinterpret_cast<unsigned*>(&h2);
        u4.w = *reinterpret_cast<unsigned*>(&h3);
        s_ww[pl][v] = u4;
        reinterpret_cast<int*>(&s_off4[pl])[v] = (by*Wf + bx) * 16;   // uint4 units
    }
    __syncthreads();

    // -------- Phase 2: 4-point grouped gather, MLP=4 --------
    {
        const int w    = tid >> 5;
        const int lane = tid & 31;
        const int p    = lane >> 3;          // point within group of 4
        const int q    = lane & 7;           // chpair half-index
        const uint4* qb = g_Q + (size_t)(b*Vn)*QV;
        const __half2 hz = __floats2half2_rn(0.f, 0.f);

        #pragma unroll
        for (int g = 0; g < 2; g++) {
            const int pl = w*8 + g*4 + p;
            const int4 offs = s_off4[pl];
            __half2 aAE = hz, aAO = hz, aBE = hz, aBO = hz;

            {   // views 0 & 1
                const uint4 dA0 = __ldg(qb + 0*QV + offs.x + q);
                const uint4 dB0 = __ldg(qb + 0*QV + offs.x + q + 8);
                const uint4 dA1 = __ldg(qb + 1*QV + offs.y + q);
                const uint4 dB1 = __ldg(qb + 1*QV + offs.y + q + 8);
                const uint4 w0 = s_ww[pl][0];
                FMA4(aAE, w0, dA0); FMA4(aBE, w0, dB0);
                const uint4 w1 = s_ww[pl][1];
                FMA4(aAO, w1, dA1); FMA4(aBO, w1, dB1);
            }
            {   // views 2 & 3
                const uint4 dA2 = __ldg(qb + 2*QV + offs.z + q);
                const uint4 dB2 = __ldg(qb + 2*QV + offs.z + q + 8);
                const uint4 dA3 = __ldg(qb + 3*QV + offs.w + q);
                const uint4 dB3 = __ldg(qb + 3*QV + offs.w + q + 8);
                const uint4 w2 = s_ww[pl][2];
                FMA4(aAE, w2, dA2); FMA4(aBE, w2, dB2);
                const uint4 w3 = s_ww[pl][3];
                FMA4(aAO, w3, dA3); FMA4(aBO, w3, dB3);
            }

            const __half2 sA = __hadd2(aAE, aAO);
            const __half2 sB = __hadd2(aBE, aBO);
            const float2 fA = __half22float2(sA);
            const float2 fB = __half22float2(sB);
            s_acc[pl][2*q     ] = fA.x;
            s_acc[pl][2*q + 1 ] = fA.y;
            s_acc[pl][2*q + 16] = fB.x;
            s_acc[pl][2*q + 17] = fB.y;
        }
    }
    __syncthreads();

    // -------- Phase 3: conflict-free LDS + coalesced STG.32 --------
    {
        const int w  = tid >> 5;
        const int xl = tid & 31;
        #pragma unroll
        for (int k = 0; k < 8; k++) {
            const int c  = (w*8 + k) >> 2;
            const int yl = (w*8 + k) & 3;
            const float val = s_acc[yl*32 + xl][c];
            out[((size_t)(b*Cn + c) << 18) + z0t*4096 + (y0t + yl)*64 + x0t + xl] = val;
        }
    }
}

// ---------------------------------------------------------------------------
extern "C" void kernel_launch(void* const* d_in, const int* in_sizes, int n_in,
                              void* d_out, int out_size) {
    const float* feat = (const float*)d_in[0];
    const float* R    = (const float*)d_in[1];
    const float* T    = (const float*)d_in[2];
    const float* K    = (const float*)d_in[3];
    const float* root = (const float*)d_in[4];
    float* out = (float*)d_out;

    pack_kernel<<<Bz*Vn*64, 512>>>(feat, R, T, K, root);
    sample_kernel<<<Bz*2048, 512>>>(out);
}

// round 12
// speedup vs baseline: 1.6401x; 1.0044x over previous
#include <cuda_runtime.h>
#include <cuda_fp16.h>

#define Bz 2
#define Vn 4
#define Cn 32
#define Hf 64
#define Wf 64
#define Dv 64
#define QV 65536            // uint4 (16B) units per view: 4096 texels x 16 chpairs

// Q layout: [bv][tex][chpair(16)][tap(4)][ch(2)] fp16; texel record = 256B
__device__ uint4 g_Q[Bz*Vn*QV];              // 8 MB
__device__ float g_cam[Bz*Vn][16];

// ---------------------------------------------------------------------------
// Pack: f [bv][c][y][x] fp32 -> g_Q. Block = (bv, y-row), 512 threads.
// Stage c-major half rows (padded 66) -> conflict-free STS; transpose on
// readback with byte_perm.
// ---------------------------------------------------------------------------
__global__ __launch_bounds__(512) void pack_kernel(
        const float* __restrict__ f,
        const float* __restrict__ R, const float* __restrict__ T,
        const float* __restrict__ K, const float* __restrict__ root) {
    __shared__ __half s_f[2][32][66];        // [row][c][x + pad2]
    const int tid = threadIdx.x;
    const int bv  = blockIdx.x >> 6;
    const int y0  = blockIdx.x & 63;

    #pragma unroll
    for (int it = 0; it < 2; it++) {
        const int k   = tid + it*512;        // 1024: 2 rows x 32 c x 16 x4
        const int x4  = (k & 15) * 4;
        const int c   = (k >> 4) & 31;
        const int row = k >> 9;
        const int gy  = min(y0 + row, 63);
        const float4 a = __ldg(reinterpret_cast<const float4*>(
            &f[(((bv*Cn + c)*Hf) + gy)*Wf + x4]));
        const __half2 h0 = __floats2half2_rn(a.x, a.y);
        const __half2 h1 = __floats2half2_rn(a.z, a.w);
        *reinterpret_cast<__half2*>(&s_f[row][c][x4    ]) = h0;
        *reinterpret_cast<__half2*>(&s_f[row][c][x4 + 2]) = h1;
    }

    if (blockIdx.x == 0 && tid < Bz*Vn) {
        int i = tid, b = i / Vn;
        const float* Ri = R + i*9; const float* Ti = T + i*3;
        const float* Ki = K + i*9; const float* rb = root + b*3;
        float* o = g_cam[i];
        #pragma unroll
        for (int r = 0; r < 9; r++) o[r] = Ri[r];
        #pragma unroll
        for (int r = 0; r < 3; r++)
            o[9+r] = Ri[r*3+0]*rb[0] + Ri[r*3+1]*rb[1] + Ri[r*3+2]*rb[2] + Ti[r];
        o[12] = Ki[0]; o[13] = Ki[4]; o[14] = Ki[2]; o[15] = Ki[5];
    }
    __syncthreads();

    #pragma unroll
    for (int it = 0; it < 2; it++) {
        const int k = tid + it*512;          // 1024: 64 tex x 16 chpairs
        const int q = k & 15;
        const int x = (k >> 4) & 63;
        const int e  = x & ~1;
        const int i0 = x - e;                // 0 or 1
        const int i1 = min(x + 1, 63) - e;   // 1 or 2 (1 at border)

        uint4 u;
        #pragma unroll
        for (int r = 0; r < 2; r++) {
            const unsigned* rowA = reinterpret_cast<const unsigned*>(&s_f[r][2*q    ][0]);
            const unsigned* rowB = reinterpret_cast<const unsigned*>(&s_f[r][2*q + 1][0]);
            const unsigned A0 = rowA[(e >> 1)    ];
            const unsigned A1 = rowA[(e >> 1) + 1];
            const unsigned B0 = rowB[(e >> 1)    ];
            const unsigned B1 = rowB[(e >> 1) + 1];
            const unsigned vx = __byte_perm(A0, B0, i0 ? 0x7632 : 0x5410);
            const unsigned vy = (i1 == 2) ? __byte_perm(A1, B1, 0x5410)
                                          : __byte_perm(A0, B0, 0x7632);
            if (r == 0) { u.x = vx; u.y = vy; } else { u.z = vx; u.w = vy; }
        }
        g_Q[bv*QV + (y0*64 + x)*16 + q] = u;
    }
}

#define FMA4(acc, ww, d)                                                              \
    acc = __hfma2(*reinterpret_cast<const __half2*>(&(ww).x),                         \
                  *reinterpret_cast<const __half2*>(&(d).x), acc);                    \
    acc = __hfma2(*reinterpret_cast<const __half2*>(&(ww).y),                         \
                  *reinterpret_cast<const __half2*>(&(d).y), acc);                    \
    acc = __hfma2(*reinterpret_cast<const __half2*>(&(ww).z),                         \
                  *reinterpret_cast<const __half2*>(&(d).z), acc);                    \
    acc = __hfma2(*reinterpret_cast<const __half2*>(&(ww).w),                         \
                  *reinterpret_cast<const __half2*>(&(d).w), acc);

// ---------------------------------------------------------------------------
// Main kernel. Tile 32(x) x 4(y) x 1(z), 512 threads, 3 blocks/SM.
// Phase 2: 4-pt grouped gather (MLP=4), HFMA2, swizzled conflict-free s_acc.
// ---------------------------------------------------------------------------
__global__ __launch_bounds__(512, 3) void sample_kernel(float* __restrict__ out) {
    __shared__ float s_cam[128];
    __shared__ uint4 s_ww[128][Vn];
    __shared__ int4  s_off4[128];
    __shared__ float s_acc[128][Cn + 1];

    const int tid = threadIdx.x;
    const int bid = blockIdx.x;
    const int b   = bid >> 11;
    const int t   = bid & 2047;
    const int x0t = (t & 1) * 32;
    const int y0t = ((t >> 1) & 15) * 4;
    const int z0t = t >> 5;

    if (tid < 128) s_cam[tid] = reinterpret_cast<const float*>(g_cam)[b*64 + tid];
    __syncthreads();

    // -------- Phase 1: projection + weight remap --------
    {
        const int pl = tid >> 2;
        const int v  = tid & 3;
        const int xi = x0t + (pl & 31);
        const int yi = y0t + (pl >> 5);
        const int zi = z0t;

        const float wx = (xi * (1.0f/63.0f) - 0.5f) * 0.2f;
        const float wy = (yi * (1.0f/63.0f) - 0.5f) * 0.2f;
        const float wz = (zi * (1.0f/63.0f) - 0.5f) * 0.2f;

        const float* cam = &s_cam[v*16];
        const float Xc = cam[0]*wx + cam[1]*wy + cam[2]*wz + cam[9];
        const float Yc = cam[3]*wx + cam[4]*wy + cam[5]*wz + cam[10];
        const float Zc = cam[6]*wx + cam[7]*wy + cam[8]*wz + cam[11];
        const float zc = fmaxf(Zc, 1e-5f);

        const float rz = __fdividef(1.0f, zc);
        const float u  = Xc * cam[12] * rz + cam[14];
        const float vv = Yc * cam[13] * rz + cam[15];
        const float px = u  * (64.0f/255.0f) - 0.5f;
        const float py = vv * (64.0f/255.0f) - 0.5f;

        const float x0f = floorf(px), y0f = floorf(py);
        const float fx1 = px - x0f,   fy1 = py - y0f;
        const float fx0 = 1.0f - fx1, fy0 = 1.0f - fy1;
        const int ix0 = (int)x0f, iy0 = (int)y0f;
        const int ix1 = ix0 + 1,  iy1 = iy0 + 1;

        const float mx0 = (ix0 >= 0 && ix0 < Wf) ? fx0 : 0.0f;
        const float mx1 = (ix1 >= 0 && ix1 < Wf) ? fx1 : 0.0f;
        const float my0 = (iy0 >= 0 && iy0 < Hf) ? fy0 * 0.25f : 0.0f;
        const float my1 = (iy1 >= 0 && iy1 < Hf) ? fy1 * 0.25f : 0.0f;

        const int bx = min(max(ix0, 0), Wf-2);
        const int by = min(max(iy0, 0), Hf-2);
        const float wqx0 = (ix0 == bx)   ? mx0 : ((ix1 == bx)   ? mx1 : 0.0f);
        const float wqx1 = (ix1 == bx+1) ? mx1 : ((ix0 == bx+1) ? mx0 : 0.0f);
        const float wqy0 = (iy0 == by)   ? my0 : ((iy1 == by)   ? my1 : 0.0f);
        const float wqy1 = (iy1 == by+1) ? my1 : ((iy0 == by+1) ? my0 : 0.0f);

        const float w0 = wqy0*wqx0, w1 = wqy0*wqx1, w2 = wqy1*wqx0, w3 = wqy1*wqx1;
        __half2 h0 = __floats2half2_rn(w0, w0);
        __half2 h1 = __floats2half2_rn(w1, w1);
        __half2 h2 = __floats2half2_rn(w2, w2);
        __half2 h3 = __floats2half2_rn(w3, w3);
        uint4 u4;
        u4.x = *reinterpret_cast<unsigned*>(&h0);
        u4.y = *reinterpret_cast<unsigned*>(&h1);
        u4.z = *reinterpret_cast<unsigned*>(&h2);
        u4.w = *reinterpret_cast<unsigned*>(&h3);
        s_ww[pl][v] = u4;
        reinterpret_cast<int*>(&s_off4[pl])[v] = (by*Wf + bx) * 16;
    }
    __syncthreads();

    // -------- Phase 2: 4-point grouped gather, MLP=4, swizzled STS --------
    {
        const int w    = tid >> 5;
        const int lane = tid & 31;
        const int p    = lane >> 3;          // point within group of 4
        const int q    = lane & 7;           // chpair half-index
        const uint4* qb = g_Q + (size_t)(b*Vn)*QV;
        const __half2 hz = __floats2half2_rn(0.f, 0.f);
        // swizzle shift: t(p) - p with t(p) = ((p&1)<<4)|(p>>1) in {0,16,1,17}
        const int swv = (((p & 1) << 4) | (p >> 1)) - p;

        #pragma unroll
        for (int g = 0; g < 2; g++) {
            const int pl = w*8 + g*4 + p;
            const int4 offs = s_off4[pl];
            __half2 aAE = hz, aAO = hz, aBE = hz, aBO = hz;

            {   // views 0 & 1
                const uint4 dA0 = __ldg(qb + 0*QV + offs.x + q);
                const uint4 dB0 = __ldg(qb + 0*QV + offs.x + q + 8);
                const uint4 dA1 = __ldg(qb + 1*QV + offs.y + q);
                const uint4 dB1 = __ldg(qb + 1*QV + offs.y + q + 8);
                const uint4 w0 = s_ww[pl][0];
                FMA4(aAE, w0, dA0); FMA4(aBE, w0, dB0);
                const uint4 w1 = s_ww[pl][1];
                FMA4(aAO, w1, dA1); FMA4(aBO, w1, dB1);
            }
            {   // views 2 & 3
                const uint4 dA2 = __ldg(qb + 2*QV + offs.z + q);
                const uint4 dB2 = __ldg(qb + 2*QV + offs.z + q + 8);
                const uint4 dA3 = __ldg(qb + 3*QV + offs.w + q);
                const uint4 dB3 = __ldg(qb + 3*QV + offs.w + q + 8);
                const uint4 w2 = s_ww[pl][2];
                FMA4(aAE, w2, dA2); FMA4(aBE, w2, dB2);
                const uint4 w3 = s_ww[pl][3];
                FMA4(aAO, w3, dA3); FMA4(aBO, w3, dB3);
            }

            const __half2 sA = __hadd2(aAE, aAO);
            const __half2 sB = __hadd2(aBE, aBO);
            const float2 fA = __half22float2(sA);
            const float2 fB = __half22float2(sB);
            s_acc[pl][(2*q      + swv) & 31] = fA.x;
            s_acc[pl][(2*q + 1  + swv) & 31] = fA.y;
            s_acc[pl][(2*q + 16 + swv) & 31] = fB.x;
            s_acc[pl][(2*q + 17 + swv) & 31] = fB.y;
        }
    }
    __syncthreads();

    // -------- Phase 3: swizzled conflict-free LDS + coalesced STG.32 --------
    {
        const int w  = tid >> 5;
        const int xl = tid & 31;
        const int p3 = xl & 3;
        const int swv3 = (((p3 & 1) << 4) | (p3 >> 1)) - p3;
        #pragma unroll
        for (int k = 0; k < 8; k++) {
            const int c  = (w*8 + k) >> 2;
            const int yl = (w*8 + k) & 3;
            const float val = s_acc[yl*32 + xl][(c + swv3) & 31];
            out[((size_t)(b*Cn + c) << 18) + z0t*4096 + (y0t + yl)*64 + x0t + xl] = val;
        }
    }
}

// ---------------------------------------------------------------------------
extern "C" void kernel_launch(void* const* d_in, const int* in_sizes, int n_in,
                              void* d_out, int out_size) {
    const float* feat = (const float*)d_in[0];
    const float* R    = (const float*)d_in[1];
    const float* T    = (const float*)d_in[2];
    const float* K    = (const float*)d_in[3];
    const float* root = (const float*)d_in[4];
    float* out = (float*)d_out;

    pack_kernel<<<Bz*Vn*64, 512>>>(feat, R, T, K, root);
    sample_kernel<<<Bz*2048, 512>>>(out);
}

// round 13
// speedup vs baseline: 1.7015x; 1.0374x over previous
#include <cuda_runtime.h>
#include <cuda_fp16.h>

#define Bz 2
#define Vn 4
#define Cn 32
#define Hf 64
#define Wf 64
#define Dv 64
#define QV 65536            // uint4 (16B) units per view: 4096 texels x 16 chpairs

// Q layout: [bv][tex][chpair(16)][tap(4)][ch(2)] fp16; texel record = 256B
__device__ uint4 g_Q[Bz*Vn*QV];              // 8 MB
__device__ float g_cam[Bz*Vn][16];

// ---------------------------------------------------------------------------
// Pack (R12 version — fast): f [bv][c][y][x] fp32 -> g_Q. Block = (bv, y-row),
// 512 threads. Stage c-major half rows (pad 66) -> conflict-free STS;
// byte_perm transpose on readback.
// ---------------------------------------------------------------------------
__global__ __launch_bounds__(512) void pack_kernel(
        const float* __restrict__ f,
        const float* __restrict__ R, const float* __restrict__ T,
        const float* __restrict__ K, const float* __restrict__ root) {
    __shared__ __half s_f[2][32][66];        // [row][c][x + pad2]
    const int tid = threadIdx.x;
    const int bv  = blockIdx.x >> 6;
    const int y0  = blockIdx.x & 63;

    #pragma unroll
    for (int it = 0; it < 2; it++) {
        const int k   = tid + it*512;        // 1024: 2 rows x 32 c x 16 x4
        const int x4  = (k & 15) * 4;
        const int c   = (k >> 4) & 31;
        const int row = k >> 9;
        const int gy  = min(y0 + row, 63);
        const float4 a = __ldg(reinterpret_cast<const float4*>(
            &f[(((bv*Cn + c)*Hf) + gy)*Wf + x4]));
        const __half2 h0 = __floats2half2_rn(a.x, a.y);
        const __half2 h1 = __floats2half2_rn(a.z, a.w);
        *reinterpret_cast<__half2*>(&s_f[row][c][x4    ]) = h0;
        *reinterpret_cast<__half2*>(&s_f[row][c][x4 + 2]) = h1;
    }

    if (blockIdx.x == 0 && tid < Bz*Vn) {
        int i = tid, b = i / Vn;
        const float* Ri = R + i*9; const float* Ti = T + i*3;
        const float* Ki = K + i*9; const float* rb = root + b*3;
        float* o = g_cam[i];
        #pragma unroll
        for (int r = 0; r < 9; r++) o[r] = Ri[r];
        #pragma unroll
        for (int r = 0; r < 3; r++)
            o[9+r] = Ri[r*3+0]*rb[0] + Ri[r*3+1]*rb[1] + Ri[r*3+2]*rb[2] + Ti[r];
        o[12] = Ki[0]; o[13] = Ki[4]; o[14] = Ki[2]; o[15] = Ki[5];
    }
    __syncthreads();

    #pragma unroll
    for (int it = 0; it < 2; it++) {
        const int k = tid + it*512;          // 1024: 64 tex x 16 chpairs
        const int q = k & 15;
        const int x = (k >> 4) & 63;
        const int e  = x & ~1;
        const int i0 = x - e;                // 0 or 1
        const int i1 = min(x + 1, 63) - e;   // 1 or 2 (1 at border)

        uint4 u;
        #pragma unroll
        for (int r = 0; r < 2; r++) {
            const unsigned* rowA = reinterpret_cast<const unsigned*>(&s_f[r][2*q    ][0]);
            const unsigned* rowB = reinterpret_cast<const unsigned*>(&s_f[r][2*q + 1][0]);
            const unsigned A0 = rowA[(e >> 1)    ];
            const unsigned A1 = rowA[(e >> 1) + 1];
            const unsigned B0 = rowB[(e >> 1)    ];
            const unsigned B1 = rowB[(e >> 1) + 1];
            const unsigned vx = __byte_perm(A0, B0, i0 ? 0x7632 : 0x5410);
            const unsigned vy = (i1 == 2) ? __byte_perm(A1, B1, 0x5410)
                                          : __byte_perm(A0, B0, 0x7632);
            if (r == 0) { u.x = vx; u.y = vy; } else { u.z = vx; u.w = vy; }
        }
        g_Q[bv*QV + (y0*64 + x)*16 + q] = u;
    }
}

#define FMA4(acc, ww, d)                                                              \
    acc = __hfma2(*reinterpret_cast<const __half2*>(&(ww).x),                         \
                  *reinterpret_cast<const __half2*>(&(d).x), acc);                    \
    acc = __hfma2(*reinterpret_cast<const __half2*>(&(ww).y),                         \
                  *reinterpret_cast<const __half2*>(&(d).y), acc);                    \
    acc = __hfma2(*reinterpret_cast<const __half2*>(&(ww).z),                         \
                  *reinterpret_cast<const __half2*>(&(d).z), acc);                    \
    acc = __hfma2(*reinterpret_cast<const __half2*>(&(ww).w),                         \
                  *reinterpret_cast<const __half2*>(&(d).w), acc);

// ---------------------------------------------------------------------------
// Main kernel (R11 version — fastest measured). Tile 32x4x1, 512 thr, 3/SM.
// ---------------------------------------------------------------------------
__global__ __launch_bounds__(512, 3) void sample_kernel(float* __restrict__ out) {
    __shared__ float s_cam[128];
    __shared__ uint4 s_ww[128][Vn];          // 4 x half2(w,w) per (pl, v)
    __shared__ int4  s_off4[128];            // per point: offsets for 4 views
    __shared__ float s_acc[128][Cn + 1];

    const int tid = threadIdx.x;
    const int bid = blockIdx.x;
    const int b   = bid >> 11;
    const int t   = bid & 2047;
    const int x0t = (t & 1) * 32;
    const int y0t = ((t >> 1) & 15) * 4;
    const int z0t = t >> 5;

    if (tid < 128) s_cam[tid] = reinterpret_cast<const float*>(g_cam)[b*64 + tid];
    __syncthreads();

    // -------- Phase 1: projection + weight remap --------
    {
        const int pl = tid >> 2;
        const int v  = tid & 3;
        const int xi = x0t + (pl & 31);
        const int yi = y0t + (pl >> 5);
        const int zi = z0t;

        const float wx = (xi * (1.0f/63.0f) - 0.5f) * 0.2f;
        const float wy = (yi * (1.0f/63.0f) - 0.5f) * 0.2f;
        const float wz = (zi * (1.0f/63.0f) - 0.5f) * 0.2f;

        const float* cam = &s_cam[v*16];
        const float Xc = cam[0]*wx + cam[1]*wy + cam[2]*wz + cam[9];
        const float Yc = cam[3]*wx + cam[4]*wy + cam[5]*wz + cam[10];
        const float Zc = cam[6]*wx + cam[7]*wy + cam[8]*wz + cam[11];
        const float zc = fmaxf(Zc, 1e-5f);

        const float u  = (Xc * cam[12]) / zc + cam[14];
        const float vv = (Yc * cam[13]) / zc + cam[15];
        const float px = u  * (64.0f/255.0f) - 0.5f;
        const float py = vv * (64.0f/255.0f) - 0.5f;

        const float x0f = floorf(px), y0f = floorf(py);
        const float fx1 = px - x0f,   fy1 = py - y0f;
        const float fx0 = 1.0f - fx1, fy0 = 1.0f - fy1;
        const int ix0 = (int)x0f, iy0 = (int)y0f;
        const int ix1 = ix0 + 1,  iy1 = iy0 + 1;

        const float mx0 = (ix0 >= 0 && ix0 < Wf) ? fx0 : 0.0f;
        const float mx1 = (ix1 >= 0 && ix1 < Wf) ? fx1 : 0.0f;
        const float my0 = (iy0 >= 0 && iy0 < Hf) ? fy0 * 0.25f : 0.0f;
        const float my1 = (iy1 >= 0 && iy1 < Hf) ? fy1 * 0.25f : 0.0f;

        const int bx = min(max(ix0, 0), Wf-2);
        const int by = min(max(iy0, 0), Hf-2);
        const float wqx0 = (ix0 == bx)   ? mx0 : ((ix1 == bx)   ? mx1 : 0.0f);
        const float wqx1 = (ix1 == bx+1) ? mx1 : ((ix0 == bx+1) ? mx0 : 0.0f);
        const float wqy0 = (iy0 == by)   ? my0 : ((iy1 == by)   ? my1 : 0.0f);
        const float wqy1 = (iy1 == by+1) ? my1 : ((iy0 == by+1) ? my0 : 0.0f);

        const float w0 = wqy0*wqx0, w1 = wqy0*wqx1, w2 = wqy1*wqx0, w3 = wqy1*wqx1;
        __half2 h0 = __floats2half2_rn(w0, w0);
        __half2 h1 = __floats2half2_rn(w1, w1);
        __half2 h2 = __floats2half2_rn(w2, w2);
        __half2 h3 = __floats2half2_rn(w3, w3);
        uint4 u4;
        u4.x = *reinterpret_cast<unsigned*>(&h0);
        u4.y = *reinterpret_cast<unsigned*>(&h1);
        u4.z = *reinterpret_cast<unsigned*>(&h2);
        u4.w = *reinterpret_cast<unsigned*>(&h3);
        s_ww[pl][v] = u4;
        reinterpret_cast<int*>(&s_off4[pl])[v] = (by*Wf + bx) * 16;   // uint4 units
    }
    __syncthreads();

    // -------- Phase 2: 4-point grouped gather, MLP=4 --------
    {
        const int w    = tid >> 5;
        const int lane = tid & 31;
        const int p    = lane >> 3;          // point within group of 4
        const int q    = lane & 7;           // chpair half-index
        const uint4* qb = g_Q + (size_t)(b*Vn)*QV;
        const __half2 hz = __floats2half2_rn(0.f, 0.f);

        #pragma unroll
        for (int g = 0; g < 2; g++) {
            const int pl = w*8 + g*4 + p;
            const int4 offs = s_off4[pl];
            __half2 aAE = hz, aAO = hz, aBE = hz, aBO = hz;

            {   // views 0 & 1
                const uint4 dA0 = __ldg(qb + 0*QV + offs.x + q);
                const uint4 dB0 = __ldg(qb + 0*QV + offs.x + q + 8);
                const uint4 dA1 = __ldg(qb + 1*QV + offs.y + q);
                const uint4 dB1 = __ldg(qb + 1*QV + offs.y + q + 8);
                const uint4 w0 = s_ww[pl][0];
                FMA4(aAE, w0, dA0); FMA4(aBE, w0, dB0);
                const uint4 w1 = s_ww[pl][1];
                FMA4(aAO, w1, dA1); FMA4(aBO, w1, dB1);
            }
            {   // views 2 & 3
                const uint4 dA2 = __ldg(qb + 2*QV + offs.z + q);
                const uint4 dB2 = __ldg(qb + 2*QV + offs.z + q + 8);
                const uint4 dA3 = __ldg(qb + 3*QV + offs.w + q);
                const uint4 dB3 = __ldg(qb + 3*QV + offs.w + q + 8);
                const uint4 w2 = s_ww[pl][2];
                FMA4(aAE, w2, dA2); FMA4(aBE, w2, dB2);
                const uint4 w3 = s_ww[pl][3];
                FMA4(aAO, w3, dA3); FMA4(aBO, w3, dB3);
            }

            const __half2 sA = __hadd2(aAE, aAO);
            const __half2 sB = __hadd2(aBE, aBO);
            const float2 fA = __half22float2(sA);
            const float2 fB = __half22float2(sB);
            s_acc[pl][2*q     ] = fA.x;
            s_acc[pl][2*q + 1 ] = fA.y;
            s_acc[pl][2*q + 16] = fB.x;
            s_acc[pl][2*q + 17] = fB.y;
        }
    }
    __syncthreads();

    // -------- Phase 3: conflict-free LDS + coalesced STG.32 --------
    {
        const int w  = tid >> 5;
        const int xl = tid & 31;
        #pragma unroll
        for (int k = 0; k < 8; k++) {
            const int c  = (w*8 + k) >> 2;
            const int yl = (w*8 + k) & 3;
            const float val = s_acc[yl*32 + xl][c];
            out[((size_t)(b*Cn + c) << 18) + z0t*4096 + (y0t + yl)*64 + x0t + xl] = val;
        }
    }
}

// ---------------------------------------------------------------------------
extern "C" void kernel_launch(void* const* d_in, const int* in_sizes, int n_in,
                              void* d_out, int out_size) {
    const float* feat = (const float*)d_in[0];
    const float* R    = (const float*)d_in[1];
    const float* T    = (const float*)d_in[2];
    const float* K    = (const float*)d_in[3];
    const float* root = (const float*)d_in[4];
    float* out = (float*)d_out;

    pack_kernel<<<Bz*Vn*64, 512>>>(feat, R, T, K, root);
    sample_kernel<<<Bz*2048, 512>>>(out);
}